// round 13
// baseline (speedup 1.0000x reference)
#include <cuda_runtime.h>
#include <cuda_bf16.h>
#include <math.h>
#include <stdint.h>

#define B_  32
#define T_  64
#define V_  32000
#define D_  512
#define E_  1024
#define H_  1024
#define G4  4096      // 4*H
#define TB  2048      // T*B

// ---------------- device scratch (no allocations allowed) ----------------
__device__ float d_enc_pre[B_ * G4];                  // 0.5 MB
__device__ float d_pre[TB * G4];                      // 32 MB
__device__ float d_hx[(T_ + 1) * B_ * H_];            // 8.5 MB (slot0 unused)
__device__ unsigned g_bar;
__device__ __nv_bfloat16 d_Ah[TB * H_];               // 4 MB  hx hi
__device__ __nv_bfloat16 d_Al[TB * H_];               // 4 MB  hx lo
__device__ __nv_bfloat16 d_Bh[(size_t)V_ * H_];       // 64 MB W_fc hi
__device__ __nv_bfloat16 d_Bl[(size_t)V_ * H_];       // 64 MB W_fc lo
__device__ unsigned long long d_amax[TB];             // packed (val, ~col)

// ======================= PTX helpers (base-target, no 'a' features) ======
__device__ __forceinline__ uint32_t smem_u32(const void* p) {
    uint32_t a;
    asm("{ .reg .u64 t; cvta.to.shared.u64 t, %1; cvt.u32.u64 %0, t; }"
        : "=r"(a) : "l"(p));
    return a;
}
__device__ __forceinline__ void ldsm_x4(uint32_t& r0, uint32_t& r1,
                                        uint32_t& r2, uint32_t& r3, uint32_t a) {
    asm volatile("ldmatrix.sync.aligned.m8n8.x4.shared.b16 {%0,%1,%2,%3}, [%4];"
                 : "=r"(r0), "=r"(r1), "=r"(r2), "=r"(r3) : "r"(a));
}
__device__ __forceinline__ void mma16816(float* c,
    uint32_t a0, uint32_t a1, uint32_t a2, uint32_t a3, uint32_t b0, uint32_t b1) {
    asm volatile("mma.sync.aligned.m16n8k16.row.col.f32.bf16.bf16.f32 "
                 "{%0,%1,%2,%3}, {%4,%5,%6,%7}, {%8,%9}, {%0,%1,%2,%3};"
                 : "+f"(c[0]), "+f"(c[1]), "+f"(c[2]), "+f"(c[3])
                 : "r"(a0), "r"(a1), "r"(a2), "r"(a3), "r"(b0), "r"(b1));
}
// packed fp32x2 FMA (Blackwell base ISA; ptxas never auto-emits FFMA2)
__device__ __forceinline__ void ffma2(uint64_t& d, uint64_t a, uint64_t b) {
    asm("fma.rn.f32x2 %0, %1, %2, %0;" : "+l"(d) : "l"(a), "l"(b));
}
__device__ __forceinline__ uint64_t splat2(float a) {
    uint64_t r;
    asm("mov.b64 %0, {%1, %1};" : "=l"(r) : "f"(a));
    return r;
}
__device__ __forceinline__ float2 unpack2(uint64_t v) {
    float2 f;
    asm("mov.b64 {%0, %1}, %2;" : "=f"(f.x), "=f"(f.y) : "l"(v));
    return f;
}
// monotone float->uint (order-preserving)
__device__ __forceinline__ uint32_t fmono(float f) {
    uint32_t u = __float_as_uint(f);
    return (u & 0x80000000u) ? ~u : (u | 0x80000000u);
}

// ---------------- W_fc fp32 -> (hi, lo) bf16 split (side stream) ----------
__global__ __launch_bounds__(256) void conv_wfc(const float* __restrict__ W)
{
    size_t i = (size_t)blockIdx.x * 256 + threadIdx.x;   // float4 index
    float4 v = ((const float4*)W)[i];
    __nv_bfloat16 h0 = __float2bfloat16(v.x);
    __nv_bfloat16 h1 = __float2bfloat16(v.y);
    __nv_bfloat16 h2 = __float2bfloat16(v.z);
    __nv_bfloat16 h3 = __float2bfloat16(v.w);
    __nv_bfloat16 l0 = __float2bfloat16(v.x - __bfloat162float(h0));
    __nv_bfloat16 l1 = __float2bfloat16(v.y - __bfloat162float(h1));
    __nv_bfloat16 l2 = __float2bfloat16(v.z - __bfloat162float(h2));
    __nv_bfloat16 l3 = __float2bfloat16(v.w - __bfloat162float(h3));
    struct bf4 { __nv_bfloat16 a, b, c, d; };
    *(bf4*)(d_Bh + 4 * i) = bf4{h0, h1, h2, h3};
    *(bf4*)(d_Bl + 4 * i) = bf4{l0, l1, l2, l3};
}

// ---------------- enc_pre + replay-state init (fused) ---------------------
// enc_pre[b,j] = b_ih[j]+b_hh[j] + sum_e enc[b,e]*W_ih[j,e]
// also zeros d_amax and g_bar (must run before rec/logits each replay).
__global__ __launch_bounds__(256) void enc_pre_kernel(
    const float* __restrict__ enc, const float* __restrict__ Wih,
    const float* __restrict__ bih, const float* __restrict__ bhh)
{
    int tid = threadIdx.x;
    int gidx = blockIdx.x * 256 + tid;
    if (gidx < TB) d_amax[gidx] = 0ull;
    if (gidx == 0) g_bar = 0u;

    __shared__ float As[32][36];
    __shared__ float Bs[32][36];
    int j0  = blockIdx.x * 32;
    int lr  = tid >> 3, lk = (tid & 7) * 4;
    int col = tid & 31, rg = (tid >> 5) * 4;
    float acc[4] = {0.f, 0.f, 0.f, 0.f};

    for (int k0 = 0; k0 < E_; k0 += 32) {
        float4 av = *(const float4*)(enc + lr * E_ + k0 + lk);
        float4 bv = *(const float4*)(Wih + (size_t)(j0 + lr) * (E_ + D_) + k0 + lk);
        As[lk+0][lr] = av.x; As[lk+1][lr] = av.y; As[lk+2][lr] = av.z; As[lk+3][lr] = av.w;
        Bs[lk+0][lr] = bv.x; Bs[lk+1][lr] = bv.y; Bs[lk+2][lr] = bv.z; Bs[lk+3][lr] = bv.w;
        __syncthreads();
#pragma unroll
        for (int kk = 0; kk < 32; kk++) {
            float4 a = *(const float4*)&As[kk][rg];
            float  b = Bs[kk][col];
            acc[0] += a.x * b; acc[1] += a.y * b; acc[2] += a.z * b; acc[3] += a.w * b;
        }
        __syncthreads();
    }
    float bias = bih[j0 + col] + bhh[j0 + col];
#pragma unroll
    for (int i = 0; i < 4; i++)
        d_enc_pre[(rg + i) * G4 + j0 + col] = acc[i] + bias;
}

// ---------------- pre = emb[gather] @ W_ih[:,E:].T + enc_pre --------------
__global__ __launch_bounds__(256, 2) void pre_gemm_big(
    const float* __restrict__ emb, const int* __restrict__ gt,
    const float* __restrict__ Wih)
{
    __shared__ float As[16][132];
    __shared__ float Bs[16][132];
    int tid = threadIdx.x;
    int m0 = blockIdx.x * 128, n0 = blockIdx.y * 128;
    int lr = tid >> 2, lk4 = (tid & 3) * 4;

    int mA0 = m0 + lr, mA1 = m0 + lr + 64;
    int tok0 = gt[(mA0 & 31) * T_ + (mA0 >> 5)];
    int tok1 = gt[(mA1 & 31) * T_ + (mA1 >> 5)];
    const float* Ap0 = emb + (size_t)tok0 * D_ + lk4;
    const float* Ap1 = emb + (size_t)tok1 * D_ + lk4;
    const float* Bp0 = Wih + (size_t)(n0 + lr)      * (E_ + D_) + E_ + lk4;
    const float* Bp1 = Wih + (size_t)(n0 + lr + 64) * (E_ + D_) + E_ + lk4;

    int rm = (tid >> 4) * 8, cn = (tid & 15) * 8;
    uint64_t accp[8][4];                 // rows x packed col-pairs
#pragma unroll
    for (int i = 0; i < 8; i++)
#pragma unroll
        for (int j = 0; j < 4; j++) accp[i][j] = 0ull;

    float4 a0v = *(const float4*)(Ap0);
    float4 a1v = *(const float4*)(Ap1);
    float4 b0v = *(const float4*)(Bp0);
    float4 b1v = *(const float4*)(Bp1);

    for (int k0 = 0; k0 < D_; k0 += 16) {
        As[lk4+0][lr]    = a0v.x; As[lk4+1][lr]    = a0v.y;
        As[lk4+2][lr]    = a0v.z; As[lk4+3][lr]    = a0v.w;
        As[lk4+0][lr+64] = a1v.x; As[lk4+1][lr+64] = a1v.y;
        As[lk4+2][lr+64] = a1v.z; As[lk4+3][lr+64] = a1v.w;
        Bs[lk4+0][lr]    = b0v.x; Bs[lk4+1][lr]    = b0v.y;
        Bs[lk4+2][lr]    = b0v.z; Bs[lk4+3][lr]    = b0v.w;
        Bs[lk4+0][lr+64] = b1v.x; Bs[lk4+1][lr+64] = b1v.y;
        Bs[lk4+2][lr+64] = b1v.z; Bs[lk4+3][lr+64] = b1v.w;
        __syncthreads();

        if (k0 + 16 < D_) {
            a0v = *(const float4*)(Ap0 + k0 + 16);
            a1v = *(const float4*)(Ap1 + k0 + 16);
            b0v = *(const float4*)(Bp0 + k0 + 16);
            b1v = *(const float4*)(Bp1 + k0 + 16);
        }

#pragma unroll
        for (int kk = 0; kk < 16; kk++) {
            float4 x0 = *(const float4*)&As[kk][rm];
            float4 x1 = *(const float4*)&As[kk][rm + 4];
            ulonglong2 yb0 = *(const ulonglong2*)&Bs[kk][cn];
            ulonglong2 yb1 = *(const ulonglong2*)&Bs[kk][cn + 4];
            uint64_t bp0 = yb0.x, bp1 = yb0.y, bp2 = yb1.x, bp3 = yb1.y;
            float av[8] = {x0.x, x0.y, x0.z, x0.w, x1.x, x1.y, x1.z, x1.w};
#pragma unroll
            for (int i = 0; i < 8; i++) {
                uint64_t s = splat2(av[i]);
                ffma2(accp[i][0], s, bp0);
                ffma2(accp[i][1], s, bp1);
                ffma2(accp[i][2], s, bp2);
                ffma2(accp[i][3], s, bp3);
            }
        }
        __syncthreads();
    }

#pragma unroll
    for (int i = 0; i < 8; i++) {
        int mm = m0 + rm + i;
        float4 e0 = *(const float4*)&d_enc_pre[(mm & 31) * G4 + n0 + cn];
        float4 e1 = *(const float4*)&d_enc_pre[(mm & 31) * G4 + n0 + cn + 4];
        float2 p0 = unpack2(accp[i][0]);
        float2 p1 = unpack2(accp[i][1]);
        float2 p2 = unpack2(accp[i][2]);
        float2 p3 = unpack2(accp[i][3]);
        float4 r0 = { p0.x + e0.x, p0.y + e0.y, p1.x + e0.z, p1.y + e0.w };
        float4 r1 = { p2.x + e1.x, p2.y + e1.y, p3.x + e1.z, p3.y + e1.w };
        *(float4*)&d_pre[(size_t)mm * G4 + n0 + cn]     = r0;
        *(float4*)&d_pre[(size_t)mm * G4 + n0 + cn + 4] = r1;
    }
}

// ---------------- persistent recurrence, 512 threads, packed f32x2 --------
// t=0 skips the GEMM entirely (hx_0 == 0), so d_hx slot 0 is never touched.
__global__ __launch_bounds__(512, 1) void rec_persist(const float* __restrict__ Whh)
{
    extern __shared__ float smem[];
    float* s_hx = smem;             // [32][1024]  128KB
    float* red  = smem + 32768;     // [32][16][32] 64KB

    int tid = threadIdx.x;
    int col = tid & 31;             // gate column within block (g*8+hh)
    int kg  = tid >> 5;             // K-slice 0..15 (64 k each)
    int g   = col >> 3, hh = col & 7;
    int hbase = blockIdx.x * 8;
    int jcol = g * H_ + hbase + hh;

    // W_hh slice packed as fp32 pairs: 64 floats = 16 x ulonglong2
    ulonglong2 w2[16];
    const ulonglong2* wp = (const ulonglong2*)(Whh + (size_t)jcol * H_) + kg * 16;
#pragma unroll
    for (int k = 0; k < 16; k++) w2[k] = wp[k];

    int b_own = tid >> 3, hh_own = tid & 7;   // valid for tid<256
    int hcol_own = hbase + hh_own;
    float creg = 0.f;

    for (int t = 0; t < T_; t++) {
        // prefetch this step's pre-gate values early (independent of hx)
        float p0 = 0.f, p1 = 0.f, p2 = 0.f, p3 = 0.f;
        if (tid < 256) {
            const float* pp = d_pre + ((size_t)(t * B_ + b_own)) * G4 + hcol_own;
            p0 = __ldg(pp);            p1 = __ldg(pp + H_);
            p2 = __ldg(pp + 2 * H_);   p3 = __ldg(pp + 3 * H_);
        }

        if (t > 0) {
            const float4* src = (const float4*)(d_hx + (size_t)t * (B_ * H_));
            float4* dst = (float4*)s_hx;
#pragma unroll
            for (int i = 0; i < 16; i++) dst[tid + i * 512] = src[tid + i * 512];
            __syncthreads();

#pragma unroll 2
            for (int b = 0; b < 32; b++) {
                const ulonglong2* hrow = (const ulonglong2*)(s_hx + b * H_ + kg * 64);
                uint64_t acc01 = 0ull, acc23 = 0ull;   // packed (+0,+0)
#pragma unroll
                for (int k = 0; k < 16; k++) {
                    ulonglong2 h = hrow[k];
                    ffma2(acc01, w2[k].x, h.x);
                    ffma2(acc23, w2[k].y, h.y);
                }
                float2 s01 = unpack2(acc01);
                float2 s23 = unpack2(acc23);
                red[b * 512 + kg * 32 + col] = (s01.x + s01.y) + (s23.x + s23.y);
            }
            __syncthreads();
        }

        if (tid < 256) {
            float gi = 0.f, gf = 0.f, gg = 0.f, go = 0.f;
            if (t > 0) {
#pragma unroll
                for (int kk = 0; kk < 16; kk++) {
                    const float* r = red + b_own * 512 + kk * 32;
                    gi += r[hh_own];      gf += r[8  + hh_own];
                    gg += r[16 + hh_own]; go += r[24 + hh_own];
                }
            }
            gi += p0; gf += p1; gg += p2; go += p3;
            float si = 1.f / (1.f + expf(-gi));
            float sf = 1.f / (1.f + expf(-gf));
            float so = 1.f / (1.f + expf(-go));
            creg = sf * creg + si * tanhf(gg);
            float hn = so * tanhf(creg);
            d_hx[(size_t)(t + 1) * (B_ * H_) + b_own * H_ + hcol_own] = hn;
            __nv_bfloat16 ah = __float2bfloat16(hn);
            __nv_bfloat16 al = __float2bfloat16(hn - __bfloat162float(ah));
            size_t arow = (size_t)(t * B_ + b_own) * H_ + hcol_own;
            d_Ah[arow] = ah; d_Al[arow] = al;
        }

        __threadfence();
        __syncthreads();
        if (tid == 0) {
            atomicAdd(&g_bar, 1u);
            unsigned target = 128u * (unsigned)(t + 1);
            while (*((volatile unsigned*)&g_bar) < target) { }
        }
        __syncthreads();
    }
}

// ---------------- tensor logits via mma.sync (bf16 hi/lo split) -----------
// At the fallback-HMMA ceiling (rt=16/SMSP): do not touch the inner loop.
#define PAD_ 40
__global__ __launch_bounds__(256, 2) void logits_mma(
    const float* __restrict__ bfc, float* __restrict__ out)
{
    __shared__ __align__(16) __nv_bfloat16 sA[2][128 * PAD_];
    __shared__ __align__(16) __nv_bfloat16 sB[2][128 * PAD_];

    int tid = threadIdx.x, lane = tid & 31, w = tid >> 5;
    int wm = w & 3, wn = w >> 2;
    int m0 = blockIdx.x * 128, n0 = blockIdx.y * 128;

    float c[2][8][4];
#pragma unroll
    for (int mi = 0; mi < 2; mi++)
#pragma unroll
        for (int ni = 0; ni < 8; ni++)
#pragma unroll
            for (int q = 0; q < 4; q++) c[mi][ni][q] = 0.f;

    int lrow = tid >> 2, lch = (tid & 3) * 8;      // loader: 2 chunks/thread

    uint4 pa[2], pb[2];
    {   // prefetch iteration 0 (seg 0, k0 0)
#pragma unroll
        for (int i = 0; i < 2; i++) {
            int row = lrow + i * 64;
            pa[i] = *(const uint4*)(d_Ah + (size_t)(m0 + row) * H_ + lch);
            pb[i] = *(const uint4*)(d_Bh + (size_t)(n0 + row) * H_ + lch);
        }
    }

    // ldsm lane addressing
    int a_col_l = (lane >> 4) * 8;
    int b_row_l = wn * 64 + ((lane >> 4) & 1) * 8 + (lane & 7);
    int b_col_l = ((lane >> 3) & 1) * 8;

    int buf = 0;
    for (int it = 0; it < 96; it++) {
        // store prefetched tile
#pragma unroll
        for (int i = 0; i < 2; i++) {
            int row = lrow + i * 64;
            *(uint4*)(&sA[buf][row * PAD_ + lch]) = pa[i];
            *(uint4*)(&sB[buf][row * PAD_ + lch]) = pb[i];
        }
        __syncthreads();

        // prefetch next k-tile while computing
        if (it + 1 < 96) {
            int nit = it + 1;
            int seg = nit >> 5;                 // 0..2
            int k0  = (nit & 31) * 32;
            const __nv_bfloat16* As = (seg == 1) ? d_Al : d_Ah;
            const __nv_bfloat16* Bs = (seg == 2) ? d_Bl : d_Bh;
#pragma unroll
            for (int i = 0; i < 2; i++) {
                int row = lrow + i * 64;
                pa[i] = *(const uint4*)(As + (size_t)(m0 + row) * H_ + k0 + lch);
                pb[i] = *(const uint4*)(Bs + (size_t)(n0 + row) * H_ + k0 + lch);
            }
        }

        // compute: 2 k16 steps
#pragma unroll
        for (int ks = 0; ks < 2; ks++) {
            uint32_t af[2][4];
#pragma unroll
            for (int mi = 0; mi < 2; mi++) {
                int row = wm * 32 + mi * 16 + (lane & 15);
                uint32_t a = smem_u32(&sA[buf][row * PAD_ + ks * 16 + a_col_l]);
                ldsm_x4(af[mi][0], af[mi][1], af[mi][2], af[mi][3], a);
            }
#pragma unroll
            for (int np = 0; np < 4; np++) {
                uint32_t b0, b1, b2, b3;
                uint32_t ba = smem_u32(
                    &sB[buf][(b_row_l + np * 16) * PAD_ + ks * 16 + b_col_l]);
                ldsm_x4(b0, b1, b2, b3, ba);
#pragma unroll
                for (int mi = 0; mi < 2; mi++) {
                    mma16816(c[mi][np * 2],     af[mi][0], af[mi][1], af[mi][2], af[mi][3], b0, b1);
                    mma16816(c[mi][np * 2 + 1], af[mi][0], af[mi][1], af[mi][2], af[mi][3], b2, b3);
                }
            }
        }
        buf ^= 1;
    }

    // epilogue: store + fused per-row argmax via packed atomicMax
#pragma unroll
    for (int mi = 0; mi < 2; mi++) {
        unsigned long long key0 = 0ull, key1 = 0ull;   // rows r0, r0+8
        int rbase = m0 + wm * 32 + mi * 16 + (lane >> 2);
#pragma unroll
        for (int ni = 0; ni < 8; ni++) {
            int col = n0 + wn * 64 + ni * 8 + (lane & 3) * 2;
            float2 bb = *(const float2*)&bfc[col];
            float2 r0 = { c[mi][ni][0] + bb.x, c[mi][ni][1] + bb.y };
            float2 r1 = { c[mi][ni][2] + bb.x, c[mi][ni][3] + bb.y };
            *(float2*)&out[(size_t)rbase * V_ + col]       = r0;
            *(float2*)&out[(size_t)(rbase + 8) * V_ + col] = r1;
            unsigned long long k;
            k = ((unsigned long long)fmono(r0.x) << 32) | (uint32_t)~col;
            if (k > key0) key0 = k;
            k = ((unsigned long long)fmono(r0.y) << 32) | (uint32_t)~(col + 1);
            if (k > key0) key0 = k;
            k = ((unsigned long long)fmono(r1.x) << 32) | (uint32_t)~col;
            if (k > key1) key1 = k;
            k = ((unsigned long long)fmono(r1.y) << 32) | (uint32_t)~(col + 1);
            if (k > key1) key1 = k;
        }
#pragma unroll
        for (int s = 1; s < 4; s <<= 1) {
            unsigned long long o0 = __shfl_xor_sync(0xFFFFFFFFu, key0, s);
            unsigned long long o1 = __shfl_xor_sync(0xFFFFFFFFu, key1, s);
            if (o0 > key0) key0 = o0;
            if (o1 > key1) key1 = o1;
        }
        if ((lane & 3) == 0) {
            atomicMax(&d_amax[rbase], key0);
            atomicMax(&d_amax[rbase + 8], key1);
        }
    }
}

// ---------------- finalize predic from packed argmax ----------------------
__global__ __launch_bounds__(256) void pred_finalize(float* __restrict__ pred)
{
    int m = blockIdx.x * 256 + threadIdx.x;
    if (m >= TB) return;
    unsigned col = ~(unsigned)(d_amax[m] & 0xFFFFFFFFull);
    int t = m >> 5, b = m & 31;
    pred[b * T_ + t] = (float)col;
}

// ------------------------------------------------------------------------
extern "C" void kernel_launch(void* const* d_in, const int* in_sizes, int n_in,
                              void* d_out, int out_size)
{
    const float* encoder = (const float*)d_in[0];
    const int*   gtruths = (const int*)  d_in[1];
    const float* emb     = (const float*)d_in[2];
    const float* W_ih    = (const float*)d_in[3];
    const float* W_hh    = (const float*)d_in[4];
    const float* b_ih    = (const float*)d_in[5];
    const float* b_hh    = (const float*)d_in[6];
    const float* W_fc    = (const float*)d_in[7];
    const float* b_fc    = (const float*)d_in[8];
    float* out = (float*)d_out;

    static cudaStream_t s2 = nullptr;
    static cudaEvent_t evA = nullptr, evB = nullptr;
    static int attr_set = 0;
    if (!attr_set) {
        cudaFuncSetAttribute(rec_persist,
                             cudaFuncAttributeMaxDynamicSharedMemorySize, 196608);
        cudaStreamCreateWithFlags(&s2, cudaStreamNonBlocking);
        cudaEventCreateWithFlags(&evA, cudaEventDisableTiming);
        cudaEventCreateWithFlags(&evB, cudaEventDisableTiming);
        attr_set = 1;
    }

    // fork: conv_wfc (only feeds logits) overlaps enc+pre+rec
    cudaEventRecord(evA, 0);
    cudaStreamWaitEvent(s2, evA, 0);
    conv_wfc<<<(int)(((size_t)V_ * H_ / 4) / 256), 256, 0, s2>>>(W_fc);
    cudaEventRecord(evB, s2);

    enc_pre_kernel<<<G4 / 32, 256>>>(encoder, W_ih, b_ih, b_hh);
    pre_gemm_big<<<dim3(TB / 128, G4 / 128), 256>>>(emb, gtruths, W_ih);
    rec_persist<<<128, 512, 196608>>>(W_hh);

    cudaStreamWaitEvent(0, evB, 0);   // join before logits (needs d_Bh/d_Bl)
    logits_mma<<<dim3(TB / 128, V_ / 128), 256>>>(b_fc, out);
    if (out_size >= TB * V_ + TB)
        pred_finalize<<<(TB + 255) / 256, 256>>>(out + (size_t)TB * V_);
}

// round 14
// speedup vs baseline: 1.0557x; 1.0557x over previous
#include <cuda_runtime.h>
#include <cuda_bf16.h>
#include <math.h>
#include <stdint.h>

#define B_  32
#define T_  64
#define V_  32000
#define D_  512
#define E_  1024
#define H_  1024
#define G4  4096      // 4*H
#define TB  2048      // T*B

// ---------------- device scratch (no allocations allowed) ----------------
__device__ float d_enc_pre[B_ * G4];                  // 0.5 MB
__device__ float d_pre[TB * G4];                      // 32 MB
__device__ float d_hx[(T_ + 1) * B_ * H_];            // 8.5 MB (slot0 unused)
__device__ unsigned g_bar;
__device__ __nv_bfloat16 d_Ah[TB * H_];               // 4 MB  hx hi
__device__ __nv_bfloat16 d_Al[TB * H_];               // 4 MB  hx lo
__device__ __nv_bfloat16 d_Bh[(size_t)V_ * H_];       // 64 MB W_fc hi
__device__ __nv_bfloat16 d_Bl[(size_t)V_ * H_];       // 64 MB W_fc lo
__device__ unsigned long long d_amax[TB];             // packed (val, ~col)

// ======================= PTX helpers (base-target, no 'a' features) ======
__device__ __forceinline__ uint32_t smem_u32(const void* p) {
    uint32_t a;
    asm("{ .reg .u64 t; cvta.to.shared.u64 t, %1; cvt.u32.u64 %0, t; }"
        : "=r"(a) : "l"(p));
    return a;
}
__device__ __forceinline__ void ldsm_x4(uint32_t& r0, uint32_t& r1,
                                        uint32_t& r2, uint32_t& r3, uint32_t a) {
    asm volatile("ldmatrix.sync.aligned.m8n8.x4.shared.b16 {%0,%1,%2,%3}, [%4];"
                 : "=r"(r0), "=r"(r1), "=r"(r2), "=r"(r3) : "r"(a));
}
__device__ __forceinline__ void mma16816(float* c,
    uint32_t a0, uint32_t a1, uint32_t a2, uint32_t a3, uint32_t b0, uint32_t b1) {
    asm volatile("mma.sync.aligned.m16n8k16.row.col.f32.bf16.bf16.f32 "
                 "{%0,%1,%2,%3}, {%4,%5,%6,%7}, {%8,%9}, {%0,%1,%2,%3};"
                 : "+f"(c[0]), "+f"(c[1]), "+f"(c[2]), "+f"(c[3])
                 : "r"(a0), "r"(a1), "r"(a2), "r"(a3), "r"(b0), "r"(b1));
}
// packed fp32x2 FMA (Blackwell base ISA; ptxas never auto-emits FFMA2)
__device__ __forceinline__ void ffma2(uint64_t& d, uint64_t a, uint64_t b) {
    asm("fma.rn.f32x2 %0, %1, %2, %0;" : "+l"(d) : "l"(a), "l"(b));
}
__device__ __forceinline__ uint64_t splat2(float a) {
    uint64_t r;
    asm("mov.b64 %0, {%1, %1};" : "=l"(r) : "f"(a));
    return r;
}
__device__ __forceinline__ float2 unpack2(uint64_t v) {
    float2 f;
    asm("mov.b64 {%0, %1}, %2;" : "=f"(f.x), "=f"(f.y) : "l"(v));
    return f;
}
__device__ __forceinline__ void cp_async16(uint32_t saddr, const void* gptr) {
    asm volatile("cp.async.cg.shared.global [%0], [%1], 16;"
                 :: "r"(saddr), "l"(gptr));
}
#define CP_COMMIT() asm volatile("cp.async.commit_group;" ::: "memory")
#define CP_WAIT0()  asm volatile("cp.async.wait_group 0;" ::: "memory")
// monotone float->uint (order-preserving)
__device__ __forceinline__ uint32_t fmono(float f) {
    uint32_t u = __float_as_uint(f);
    return (u & 0x80000000u) ? ~u : (u | 0x80000000u);
}

// ---------------- W_fc fp32 -> (hi, lo) bf16 split -----------------------
__global__ __launch_bounds__(256) void conv_wfc(const float* __restrict__ W)
{
    size_t i = (size_t)blockIdx.x * 256 + threadIdx.x;   // float4 index
    float4 v = ((const float4*)W)[i];
    __nv_bfloat16 h0 = __float2bfloat16(v.x);
    __nv_bfloat16 h1 = __float2bfloat16(v.y);
    __nv_bfloat16 h2 = __float2bfloat16(v.z);
    __nv_bfloat16 h3 = __float2bfloat16(v.w);
    __nv_bfloat16 l0 = __float2bfloat16(v.x - __bfloat162float(h0));
    __nv_bfloat16 l1 = __float2bfloat16(v.y - __bfloat162float(h1));
    __nv_bfloat16 l2 = __float2bfloat16(v.z - __bfloat162float(h2));
    __nv_bfloat16 l3 = __float2bfloat16(v.w - __bfloat162float(h3));
    struct bf4 { __nv_bfloat16 a, b, c, d; };
    *(bf4*)(d_Bh + 4 * i) = bf4{h0, h1, h2, h3};
    *(bf4*)(d_Bl + 4 * i) = bf4{l0, l1, l2, l3};
}

// ---------------- enc_pre + replay-state init (fused) ---------------------
__global__ __launch_bounds__(256) void enc_pre_kernel(
    const float* __restrict__ enc, const float* __restrict__ Wih,
    const float* __restrict__ bih, const float* __restrict__ bhh)
{
    int tid = threadIdx.x;
    int gidx = blockIdx.x * 256 + tid;
    if (gidx < TB) d_amax[gidx] = 0ull;
    if (gidx == 0) g_bar = 0u;

    __shared__ float As[32][36];
    __shared__ float Bs[32][36];
    int j0  = blockIdx.x * 32;
    int lr  = tid >> 3, lk = (tid & 7) * 4;
    int col = tid & 31, rg = (tid >> 5) * 4;
    float acc[4] = {0.f, 0.f, 0.f, 0.f};

    for (int k0 = 0; k0 < E_; k0 += 32) {
        float4 av = *(const float4*)(enc + lr * E_ + k0 + lk);
        float4 bv = *(const float4*)(Wih + (size_t)(j0 + lr) * (E_ + D_) + k0 + lk);
        As[lk+0][lr] = av.x; As[lk+1][lr] = av.y; As[lk+2][lr] = av.z; As[lk+3][lr] = av.w;
        Bs[lk+0][lr] = bv.x; Bs[lk+1][lr] = bv.y; Bs[lk+2][lr] = bv.z; Bs[lk+3][lr] = bv.w;
        __syncthreads();
#pragma unroll
        for (int kk = 0; kk < 32; kk++) {
            float4 a = *(const float4*)&As[kk][rg];
            float  b = Bs[kk][col];
            acc[0] += a.x * b; acc[1] += a.y * b; acc[2] += a.z * b; acc[3] += a.w * b;
        }
        __syncthreads();
    }
    float bias = bih[j0 + col] + bhh[j0 + col];
#pragma unroll
    for (int i = 0; i < 4; i++)
        d_enc_pre[(rg + i) * G4 + j0 + col] = acc[i] + bias;
}

// ---------------- pre = emb[gather] @ W_ih[:,E:].T + enc_pre --------------
__global__ __launch_bounds__(256, 2) void pre_gemm_big(
    const float* __restrict__ emb, const int* __restrict__ gt,
    const float* __restrict__ Wih)
{
    __shared__ float As[16][132];
    __shared__ float Bs[16][132];
    int tid = threadIdx.x;
    int m0 = blockIdx.x * 128, n0 = blockIdx.y * 128;
    int lr = tid >> 2, lk4 = (tid & 3) * 4;

    int mA0 = m0 + lr, mA1 = m0 + lr + 64;
    int tok0 = gt[(mA0 & 31) * T_ + (mA0 >> 5)];
    int tok1 = gt[(mA1 & 31) * T_ + (mA1 >> 5)];
    const float* Ap0 = emb + (size_t)tok0 * D_ + lk4;
    const float* Ap1 = emb + (size_t)tok1 * D_ + lk4;
    const float* Bp0 = Wih + (size_t)(n0 + lr)      * (E_ + D_) + E_ + lk4;
    const float* Bp1 = Wih + (size_t)(n0 + lr + 64) * (E_ + D_) + E_ + lk4;

    int rm = (tid >> 4) * 8, cn = (tid & 15) * 8;
    uint64_t accp[8][4];                 // rows x packed col-pairs
#pragma unroll
    for (int i = 0; i < 8; i++)
#pragma unroll
        for (int j = 0; j < 4; j++) accp[i][j] = 0ull;

    float4 a0v = *(const float4*)(Ap0);
    float4 a1v = *(const float4*)(Ap1);
    float4 b0v = *(const float4*)(Bp0);
    float4 b1v = *(const float4*)(Bp1);

    for (int k0 = 0; k0 < D_; k0 += 16) {
        As[lk4+0][lr]    = a0v.x; As[lk4+1][lr]    = a0v.y;
        As[lk4+2][lr]    = a0v.z; As[lk4+3][lr]    = a0v.w;
        As[lk4+0][lr+64] = a1v.x; As[lk4+1][lr+64] = a1v.y;
        As[lk4+2][lr+64] = a1v.z; As[lk4+3][lr+64] = a1v.w;
        Bs[lk4+0][lr]    = b0v.x; Bs[lk4+1][lr]    = b0v.y;
        Bs[lk4+2][lr]    = b0v.z; Bs[lk4+3][lr]    = b0v.w;
        Bs[lk4+0][lr+64] = b1v.x; Bs[lk4+1][lr+64] = b1v.y;
        Bs[lk4+2][lr+64] = b1v.z; Bs[lk4+3][lr+64] = b1v.w;
        __syncthreads();

        if (k0 + 16 < D_) {
            a0v = *(const float4*)(Ap0 + k0 + 16);
            a1v = *(const float4*)(Ap1 + k0 + 16);
            b0v = *(const float4*)(Bp0 + k0 + 16);
            b1v = *(const float4*)(Bp1 + k0 + 16);
        }

#pragma unroll
        for (int kk = 0; kk < 16; kk++) {
            float4 x0 = *(const float4*)&As[kk][rm];
            float4 x1 = *(const float4*)&As[kk][rm + 4];
            ulonglong2 yb0 = *(const ulonglong2*)&Bs[kk][cn];
            ulonglong2 yb1 = *(const ulonglong2*)&Bs[kk][cn + 4];
            uint64_t bp0 = yb0.x, bp1 = yb0.y, bp2 = yb1.x, bp3 = yb1.y;
            float av[8] = {x0.x, x0.y, x0.z, x0.w, x1.x, x1.y, x1.z, x1.w};
#pragma unroll
            for (int i = 0; i < 8; i++) {
                uint64_t s = splat2(av[i]);
                ffma2(accp[i][0], s, bp0);
                ffma2(accp[i][1], s, bp1);
                ffma2(accp[i][2], s, bp2);
                ffma2(accp[i][3], s, bp3);
            }
        }
        __syncthreads();
    }

#pragma unroll
    for (int i = 0; i < 8; i++) {
        int mm = m0 + rm + i;
        float4 e0 = *(const float4*)&d_enc_pre[(mm & 31) * G4 + n0 + cn];
        float4 e1 = *(const float4*)&d_enc_pre[(mm & 31) * G4 + n0 + cn + 4];
        float2 p0 = unpack2(accp[i][0]);
        float2 p1 = unpack2(accp[i][1]);
        float2 p2 = unpack2(accp[i][2]);
        float2 p3 = unpack2(accp[i][3]);
        float4 r0 = { p0.x + e0.x, p0.y + e0.y, p1.x + e0.z, p1.y + e0.w };
        float4 r1 = { p2.x + e1.x, p2.y + e1.y, p3.x + e1.z, p3.y + e1.w };
        *(float4*)&d_pre[(size_t)mm * G4 + n0 + cn]     = r0;
        *(float4*)&d_pre[(size_t)mm * G4 + n0 + cn + 4] = r1;
    }
}

// ---------------- persistent recurrence v3 ---------------------------------
// 512 threads, packed f32x2, half-staged hx with cp.async overlap,
// release/acquire grid barrier (no per-thread MEMBAR.GPU).
__global__ __launch_bounds__(512, 1) void rec_persist(const float* __restrict__ Whh)
{
    extern __shared__ float smem[];
    float* s_hx = smem;             // [32][1024]  128KB
    float* red  = smem + 32768;     // [32][16][32] 64KB

    int tid = threadIdx.x;
    int col = tid & 31;             // gate column within block (g*8+hh)
    int kg  = tid >> 5;             // K-slice 0..15 (64 k each)
    int g   = col >> 3, hh = col & 7;
    int hbase = blockIdx.x * 8;
    int jcol = g * H_ + hbase + hh;

    // W_hh slice packed as fp32 pairs: 64 floats = 16 x ulonglong2
    ulonglong2 w2[16];
    const ulonglong2* wp = (const ulonglong2*)(Whh + (size_t)jcol * H_) + kg * 16;
#pragma unroll
    for (int k = 0; k < 16; k++) w2[k] = wp[k];

    int b_own = tid >> 3, hh_own = tid & 7;   // valid for tid<256
    int hcol_own = hbase + hh_own;
    float creg = 0.f;
    uint32_t s_hx_u32 = smem_u32(s_hx);

    for (int t = 0; t < T_; t++) {
        // prefetch this step's pre-gate values early (independent of hx)
        float p0 = 0.f, p1 = 0.f, p2 = 0.f, p3 = 0.f;
        if (tid < 256) {
            const float* pp = d_pre + ((size_t)(t * B_ + b_own)) * G4 + hcol_own;
            p0 = __ldg(pp);            p1 = __ldg(pp + H_);
            p2 = __ldg(pp + 2 * H_);   p3 = __ldg(pp + 3 * H_);
        }

        if (t > 0) {
            const float4* src = (const float4*)(d_hx + (size_t)t * (B_ * H_));
            float4* dst = (float4*)s_hx;
            // stage half 1 (b 0..15) via LDG
#pragma unroll
            for (int i = 0; i < 8; i++) dst[tid + i * 512] = src[tid + i * 512];
            // async-stage half 2 (b 16..31) — overlaps half-1 compute
#pragma unroll
            for (int i = 0; i < 8; i++) {
                int idx = 4096 + tid + i * 512;
                cp_async16(s_hx_u32 + (uint32_t)idx * 16, src + idx);
            }
            CP_COMMIT();
            __syncthreads();

#pragma unroll 1
            for (int half = 0; half < 2; half++) {
                int bbeg = half * 16;
#pragma unroll 2
                for (int b = bbeg; b < bbeg + 16; b++) {
                    const ulonglong2* hrow =
                        (const ulonglong2*)(s_hx + b * H_ + kg * 64);
                    uint64_t a0 = 0ull, a1 = 0ull, a2 = 0ull, a3 = 0ull;
#pragma unroll
                    for (int k = 0; k < 16; k += 2) {
                        ulonglong2 h0 = hrow[k];
                        ulonglong2 h1 = hrow[k + 1];
                        ffma2(a0, w2[k].x,     h0.x);
                        ffma2(a1, w2[k].y,     h0.y);
                        ffma2(a2, w2[k + 1].x, h1.x);
                        ffma2(a3, w2[k + 1].y, h1.y);
                    }
                    float2 s0 = unpack2(a0), s1 = unpack2(a1);
                    float2 s2 = unpack2(a2), s3 = unpack2(a3);
                    red[b * 512 + kg * 32 + col] =
                        ((s0.x + s0.y) + (s1.x + s1.y)) +
                        ((s2.x + s2.y) + (s3.x + s3.y));
                }
                if (half == 0) {
                    CP_WAIT0();
                    __syncthreads();   // half-2 hx now visible
                }
            }
            __syncthreads();           // red complete
        }

        if (tid < 256) {
            float gi = 0.f, gf = 0.f, gg = 0.f, go = 0.f;
            if (t > 0) {
#pragma unroll
                for (int kk = 0; kk < 16; kk++) {
                    const float* r = red + b_own * 512 + kk * 32;
                    gi += r[hh_own];      gf += r[8  + hh_own];
                    gg += r[16 + hh_own]; go += r[24 + hh_own];
                }
            }
            gi += p0; gf += p1; gg += p2; go += p3;
            float si = 1.f / (1.f + expf(-gi));
            float sf = 1.f / (1.f + expf(-gf));
            float so = 1.f / (1.f + expf(-go));
            creg = sf * creg + si * tanhf(gg);
            float hn = so * tanhf(creg);
            d_hx[(size_t)(t + 1) * (B_ * H_) + b_own * H_ + hcol_own] = hn;
            __nv_bfloat16 ah = __float2bfloat16(hn);
            __nv_bfloat16 al = __float2bfloat16(hn - __bfloat162float(ah));
            size_t arow = (size_t)(t * B_ + b_own) * H_ + hcol_own;
            d_Ah[arow] = ah; d_Al[arow] = al;
        }

        // grid barrier: release/acquire, tid0 only (no per-thread MEMBAR)
        __syncthreads();
        if (tid == 0) {
            asm volatile("red.release.gpu.global.add.u32 [%0], %1;"
                         :: "l"(&g_bar), "r"(1u) : "memory");
            unsigned target = 128u * (unsigned)(t + 1);
            unsigned v;
            do {
                asm volatile("ld.acquire.gpu.global.u32 %0, [%1];"
                             : "=r"(v) : "l"(&g_bar) : "memory");
            } while (v < target);
        }
        __syncthreads();
    }
}

// ---------------- tensor logits via mma.sync (bf16 hi/lo split) -----------
// At the fallback-HMMA ceiling: inner loop untouched (r10/r12-proven).
#define PAD_ 40
__global__ __launch_bounds__(256, 2) void logits_mma(
    const float* __restrict__ bfc, float* __restrict__ out)
{
    __shared__ __align__(16) __nv_bfloat16 sA[2][128 * PAD_];
    __shared__ __align__(16) __nv_bfloat16 sB[2][128 * PAD_];

    int tid = threadIdx.x, lane = tid & 31, w = tid >> 5;
    int wm = w & 3, wn = w >> 2;
    int m0 = blockIdx.x * 128, n0 = blockIdx.y * 128;

    float c[2][8][4];
#pragma unroll
    for (int mi = 0; mi < 2; mi++)
#pragma unroll
        for (int ni = 0; ni < 8; ni++)
#pragma unroll
            for (int q = 0; q < 4; q++) c[mi][ni][q] = 0.f;

    int lrow = tid >> 2, lch = (tid & 3) * 8;      // loader: 2 chunks/thread

    uint4 pa[2], pb[2];
    {   // prefetch iteration 0 (seg 0, k0 0)
#pragma unroll
        for (int i = 0; i < 2; i++) {
            int row = lrow + i * 64;
            pa[i] = *(const uint4*)(d_Ah + (size_t)(m0 + row) * H_ + lch);
            pb[i] = *(const uint4*)(d_Bh + (size_t)(n0 + row) * H_ + lch);
        }
    }

    // ldsm lane addressing
    int a_col_l = (lane >> 4) * 8;
    int b_row_l = wn * 64 + ((lane >> 4) & 1) * 8 + (lane & 7);
    int b_col_l = ((lane >> 3) & 1) * 8;

    int buf = 0;
    for (int it = 0; it < 96; it++) {
        // store prefetched tile
#pragma unroll
        for (int i = 0; i < 2; i++) {
            int row = lrow + i * 64;
            *(uint4*)(&sA[buf][row * PAD_ + lch]) = pa[i];
            *(uint4*)(&sB[buf][row * PAD_ + lch]) = pb[i];
        }
        __syncthreads();

        // prefetch next k-tile while computing
        if (it + 1 < 96) {
            int nit = it + 1;
            int seg = nit >> 5;                 // 0..2
            int k0  = (nit & 31) * 32;
            const __nv_bfloat16* As = (seg == 1) ? d_Al : d_Ah;
            const __nv_bfloat16* Bs = (seg == 2) ? d_Bl : d_Bh;
#pragma unroll
            for (int i = 0; i < 2; i++) {
                int row = lrow + i * 64;
                pa[i] = *(const uint4*)(As + (size_t)(m0 + row) * H_ + k0 + lch);
                pb[i] = *(const uint4*)(Bs + (size_t)(n0 + row) * H_ + k0 + lch);
            }
        }

        // compute: 2 k16 steps
#pragma unroll
        for (int ks = 0; ks < 2; ks++) {
            uint32_t af[2][4];
#pragma unroll
            for (int mi = 0; mi < 2; mi++) {
                int row = wm * 32 + mi * 16 + (lane & 15);
                uint32_t a = smem_u32(&sA[buf][row * PAD_ + ks * 16 + a_col_l]);
                ldsm_x4(af[mi][0], af[mi][1], af[mi][2], af[mi][3], a);
            }
#pragma unroll
            for (int np = 0; np < 4; np++) {
                uint32_t b0, b1, b2, b3;
                uint32_t ba = smem_u32(
                    &sB[buf][(b_row_l + np * 16) * PAD_ + ks * 16 + b_col_l]);
                ldsm_x4(b0, b1, b2, b3, ba);
#pragma unroll
                for (int mi = 0; mi < 2; mi++) {
                    mma16816(c[mi][np * 2],     af[mi][0], af[mi][1], af[mi][2], af[mi][3], b0, b1);
                    mma16816(c[mi][np * 2 + 1], af[mi][0], af[mi][1], af[mi][2], af[mi][3], b2, b3);
                }
            }
        }
        buf ^= 1;
    }

    // epilogue: store + fused per-row argmax via packed atomicMax
#pragma unroll
    for (int mi = 0; mi < 2; mi++) {
        unsigned long long key0 = 0ull, key1 = 0ull;   // rows r0, r0+8
        int rbase = m0 + wm * 32 + mi * 16 + (lane >> 2);
#pragma unroll
        for (int ni = 0; ni < 8; ni++) {
            int col = n0 + wn * 64 + ni * 8 + (lane & 3) * 2;
            float2 bb = *(const float2*)&bfc[col];
            float2 r0 = { c[mi][ni][0] + bb.x, c[mi][ni][1] + bb.y };
            float2 r1 = { c[mi][ni][2] + bb.x, c[mi][ni][3] + bb.y };
            *(float2*)&out[(size_t)rbase * V_ + col]       = r0;
            *(float2*)&out[(size_t)(rbase + 8) * V_ + col] = r1;
            unsigned long long k;
            k = ((unsigned long long)fmono(r0.x) << 32) | (uint32_t)~col;
            if (k > key0) key0 = k;
            k = ((unsigned long long)fmono(r0.y) << 32) | (uint32_t)~(col + 1);
            if (k > key0) key0 = k;
            k = ((unsigned long long)fmono(r1.x) << 32) | (uint32_t)~col;
            if (k > key1) key1 = k;
            k = ((unsigned long long)fmono(r1.y) << 32) | (uint32_t)~(col + 1);
            if (k > key1) key1 = k;
        }
#pragma unroll
        for (int s = 1; s < 4; s <<= 1) {
            unsigned long long o0 = __shfl_xor_sync(0xFFFFFFFFu, key0, s);
            unsigned long long o1 = __shfl_xor_sync(0xFFFFFFFFu, key1, s);
            if (o0 > key0) key0 = o0;
            if (o1 > key1) key1 = o1;
        }
        if ((lane & 3) == 0) {
            atomicMax(&d_amax[rbase], key0);
            atomicMax(&d_amax[rbase + 8], key1);
        }
    }
}

// ---------------- finalize predic from packed argmax ----------------------
__global__ __launch_bounds__(256) void pred_finalize(float* __restrict__ pred)
{
    int m = blockIdx.x * 256 + threadIdx.x;
    if (m >= TB) return;
    unsigned col = ~(unsigned)(d_amax[m] & 0xFFFFFFFFull);
    int t = m >> 5, b = m & 31;
    pred[b * T_ + t] = (float)col;
}

// ------------------------------------------------------------------------
extern "C" void kernel_launch(void* const* d_in, const int* in_sizes, int n_in,
                              void* d_out, int out_size)
{
    const float* encoder = (const float*)d_in[0];
    const int*   gtruths = (const int*)  d_in[1];
    const float* emb     = (const float*)d_in[2];
    const float* W_ih    = (const float*)d_in[3];
    const float* W_hh    = (const float*)d_in[4];
    const float* b_ih    = (const float*)d_in[5];
    const float* b_hh    = (const float*)d_in[6];
    const float* W_fc    = (const float*)d_in[7];
    const float* b_fc    = (const float*)d_in[8];
    float* out = (float*)d_out;

    static int attr_set = 0;
    if (!attr_set) {
        cudaFuncSetAttribute(rec_persist,
                             cudaFuncAttributeMaxDynamicSharedMemorySize, 196608);
        attr_set = 1;
    }

    conv_wfc<<<(int)(((size_t)V_ * H_ / 4) / 256), 256>>>(W_fc);
    enc_pre_kernel<<<G4 / 32, 256>>>(encoder, W_ih, b_ih, b_hh);
    pre_gemm_big<<<dim3(TB / 128, G4 / 128), 256>>>(emb, gtruths, W_ih);
    rec_persist<<<128, 512, 196608>>>(W_hh);
    logits_mma<<<dim3(TB / 128, V_ / 128), 256>>>(b_fc, out);
    if (out_size >= TB * V_ + TB)
        pred_finalize<<<(TB + 255) / 256, 256>>>(out + (size_t)TB * V_);
}

// round 15
// speedup vs baseline: 1.2161x; 1.1520x over previous
#include <cuda_runtime.h>
#include <cuda_bf16.h>
#include <math.h>
#include <stdint.h>

#define B_  32
#define T_  64
#define V_  32000
#define D_  512
#define E_  1024
#define H_  1024
#define G4  4096      // 4*H
#define TB  2048      // T*B
#define PA  1032      // padded row stride (bf16 elems) for rec smem tiles

// ---------------- device scratch (no allocations allowed) ----------------
__device__ float d_enc_pre[B_ * G4];                  // 0.5 MB
__device__ float d_pre[TB * G4];                      // 32 MB
__device__ unsigned g_bar;
__device__ __nv_bfloat16 d_Ah[TB * H_];               // 4 MB  hx hi
__device__ __nv_bfloat16 d_Al[TB * H_];               // 4 MB  hx lo
__device__ __nv_bfloat16 d_Bh[(size_t)V_ * H_];       // 64 MB W_fc hi
__device__ __nv_bfloat16 d_Bl[(size_t)V_ * H_];       // 64 MB W_fc lo
__device__ __nv_bfloat16 d_Wh[G4 * H_];               // 8 MB  W_hh hi
__device__ __nv_bfloat16 d_Wl[G4 * H_];               // 8 MB  W_hh lo
__device__ unsigned long long d_amax[TB];             // packed (val, ~col)

// ======================= PTX helpers (base-target, no 'a' features) ======
__device__ __forceinline__ uint32_t smem_u32(const void* p) {
    uint32_t a;
    asm("{ .reg .u64 t; cvta.to.shared.u64 t, %1; cvt.u32.u64 %0, t; }"
        : "=r"(a) : "l"(p));
    return a;
}
__device__ __forceinline__ void ldsm_x4(uint32_t& r0, uint32_t& r1,
                                        uint32_t& r2, uint32_t& r3, uint32_t a) {
    asm volatile("ldmatrix.sync.aligned.m8n8.x4.shared.b16 {%0,%1,%2,%3}, [%4];"
                 : "=r"(r0), "=r"(r1), "=r"(r2), "=r"(r3) : "r"(a));
}
__device__ __forceinline__ void mma16816(float* c,
    uint32_t a0, uint32_t a1, uint32_t a2, uint32_t a3, uint32_t b0, uint32_t b1) {
    asm volatile("mma.sync.aligned.m16n8k16.row.col.f32.bf16.bf16.f32 "
                 "{%0,%1,%2,%3}, {%4,%5,%6,%7}, {%8,%9}, {%0,%1,%2,%3};"
                 : "+f"(c[0]), "+f"(c[1]), "+f"(c[2]), "+f"(c[3])
                 : "r"(a0), "r"(a1), "r"(a2), "r"(a3), "r"(b0), "r"(b1));
}
// packed fp32x2 FMA (Blackwell base ISA)
__device__ __forceinline__ void ffma2(uint64_t& d, uint64_t a, uint64_t b) {
    asm("fma.rn.f32x2 %0, %1, %2, %0;" : "+l"(d) : "l"(a), "l"(b));
}
__device__ __forceinline__ uint64_t splat2(float a) {
    uint64_t r;
    asm("mov.b64 %0, {%1, %1};" : "=l"(r) : "f"(a));
    return r;
}
__device__ __forceinline__ float2 unpack2(uint64_t v) {
    float2 f;
    asm("mov.b64 {%0, %1}, %2;" : "=f"(f.x), "=f"(f.y) : "l"(v));
    return f;
}
__device__ __forceinline__ void cp_async16(uint32_t saddr, const void* gptr) {
    asm volatile("cp.async.cg.shared.global [%0], [%1], 16;"
                 :: "r"(saddr), "l"(gptr));
}
#define CP_COMMIT() asm volatile("cp.async.commit_group;" ::: "memory")
#define CP_WAIT0()  asm volatile("cp.async.wait_group 0;" ::: "memory")
// monotone float->uint (order-preserving)
__device__ __forceinline__ uint32_t fmono(float f) {
    uint32_t u = __float_as_uint(f);
    return (u & 0x80000000u) ? ~u : (u | 0x80000000u);
}

// ---------------- W_fc fp32 -> (hi, lo) bf16 split -----------------------
__global__ __launch_bounds__(256) void conv_wfc(const float* __restrict__ W)
{
    size_t i = (size_t)blockIdx.x * 256 + threadIdx.x;
    float4 v = ((const float4*)W)[i];
    __nv_bfloat16 h0 = __float2bfloat16(v.x);
    __nv_bfloat16 h1 = __float2bfloat16(v.y);
    __nv_bfloat16 h2 = __float2bfloat16(v.z);
    __nv_bfloat16 h3 = __float2bfloat16(v.w);
    __nv_bfloat16 l0 = __float2bfloat16(v.x - __bfloat162float(h0));
    __nv_bfloat16 l1 = __float2bfloat16(v.y - __bfloat162float(h1));
    __nv_bfloat16 l2 = __float2bfloat16(v.z - __bfloat162float(h2));
    __nv_bfloat16 l3 = __float2bfloat16(v.w - __bfloat162float(h3));
    struct bf4 { __nv_bfloat16 a, b, c, d; };
    *(bf4*)(d_Bh + 4 * i) = bf4{h0, h1, h2, h3};
    *(bf4*)(d_Bl + 4 * i) = bf4{l0, l1, l2, l3};
}

// ---------------- W_hh fp32 -> (hi, lo) bf16 split -----------------------
__global__ __launch_bounds__(256) void conv_whh(const float* __restrict__ W)
{
    size_t i = (size_t)blockIdx.x * 256 + threadIdx.x;
    float4 v = ((const float4*)W)[i];
    __nv_bfloat16 h0 = __float2bfloat16(v.x);
    __nv_bfloat16 h1 = __float2bfloat16(v.y);
    __nv_bfloat16 h2 = __float2bfloat16(v.z);
    __nv_bfloat16 h3 = __float2bfloat16(v.w);
    __nv_bfloat16 l0 = __float2bfloat16(v.x - __bfloat162float(h0));
    __nv_bfloat16 l1 = __float2bfloat16(v.y - __bfloat162float(h1));
    __nv_bfloat16 l2 = __float2bfloat16(v.z - __bfloat162float(h2));
    __nv_bfloat16 l3 = __float2bfloat16(v.w - __bfloat162float(h3));
    struct bf4 { __nv_bfloat16 a, b, c, d; };
    *(bf4*)(d_Wh + 4 * i) = bf4{h0, h1, h2, h3};
    *(bf4*)(d_Wl + 4 * i) = bf4{l0, l1, l2, l3};
}

// ---------------- enc_pre + replay-state init (fused) ---------------------
__global__ __launch_bounds__(256) void enc_pre_kernel(
    const float* __restrict__ enc, const float* __restrict__ Wih,
    const float* __restrict__ bih, const float* __restrict__ bhh)
{
    int tid = threadIdx.x;
    int gidx = blockIdx.x * 256 + tid;
    if (gidx < TB) d_amax[gidx] = 0ull;
    if (gidx == 0) g_bar = 0u;

    __shared__ float As[32][36];
    __shared__ float Bs[32][36];
    int j0  = blockIdx.x * 32;
    int lr  = tid >> 3, lk = (tid & 7) * 4;
    int col = tid & 31, rg = (tid >> 5) * 4;
    float acc[4] = {0.f, 0.f, 0.f, 0.f};

    for (int k0 = 0; k0 < E_; k0 += 32) {
        float4 av = *(const float4*)(enc + lr * E_ + k0 + lk);
        float4 bv = *(const float4*)(Wih + (size_t)(j0 + lr) * (E_ + D_) + k0 + lk);
        As[lk+0][lr] = av.x; As[lk+1][lr] = av.y; As[lk+2][lr] = av.z; As[lk+3][lr] = av.w;
        Bs[lk+0][lr] = bv.x; Bs[lk+1][lr] = bv.y; Bs[lk+2][lr] = bv.z; Bs[lk+3][lr] = bv.w;
        __syncthreads();
#pragma unroll
        for (int kk = 0; kk < 32; kk++) {
            float4 a = *(const float4*)&As[kk][rg];
            float  b = Bs[kk][col];
            acc[0] += a.x * b; acc[1] += a.y * b; acc[2] += a.z * b; acc[3] += a.w * b;
        }
        __syncthreads();
    }
    float bias = bih[j0 + col] + bhh[j0 + col];
#pragma unroll
    for (int i = 0; i < 4; i++)
        d_enc_pre[(rg + i) * G4 + j0 + col] = acc[i] + bias;
}

// ---------------- pre = emb[gather] @ W_ih[:,E:].T + enc_pre --------------
__global__ __launch_bounds__(256, 2) void pre_gemm_big(
    const float* __restrict__ emb, const int* __restrict__ gt,
    const float* __restrict__ Wih)
{
    __shared__ float As[16][132];
    __shared__ float Bs[16][132];
    int tid = threadIdx.x;
    int m0 = blockIdx.x * 128, n0 = blockIdx.y * 128;
    int lr = tid >> 2, lk4 = (tid & 3) * 4;

    int mA0 = m0 + lr, mA1 = m0 + lr + 64;
    int tok0 = gt[(mA0 & 31) * T_ + (mA0 >> 5)];
    int tok1 = gt[(mA1 & 31) * T_ + (mA1 >> 5)];
    const float* Ap0 = emb + (size_t)tok0 * D_ + lk4;
    const float* Ap1 = emb + (size_t)tok1 * D_ + lk4;
    const float* Bp0 = Wih + (size_t)(n0 + lr)      * (E_ + D_) + E_ + lk4;
    const float* Bp1 = Wih + (size_t)(n0 + lr + 64) * (E_ + D_) + E_ + lk4;

    int rm = (tid >> 4) * 8, cn = (tid & 15) * 8;
    uint64_t accp[8][4];
#pragma unroll
    for (int i = 0; i < 8; i++)
#pragma unroll
        for (int j = 0; j < 4; j++) accp[i][j] = 0ull;

    float4 a0v = *(const float4*)(Ap0);
    float4 a1v = *(const float4*)(Ap1);
    float4 b0v = *(const float4*)(Bp0);
    float4 b1v = *(const float4*)(Bp1);

    for (int k0 = 0; k0 < D_; k0 += 16) {
        As[lk4+0][lr]    = a0v.x; As[lk4+1][lr]    = a0v.y;
        As[lk4+2][lr]    = a0v.z; As[lk4+3][lr]    = a0v.w;
        As[lk4+0][lr+64] = a1v.x; As[lk4+1][lr+64] = a1v.y;
        As[lk4+2][lr+64] = a1v.z; As[lk4+3][lr+64] = a1v.w;
        Bs[lk4+0][lr]    = b0v.x; Bs[lk4+1][lr]    = b0v.y;
        Bs[lk4+2][lr]    = b0v.z; Bs[lk4+3][lr]    = b0v.w;
        Bs[lk4+0][lr+64] = b1v.x; Bs[lk4+1][lr+64] = b1v.y;
        Bs[lk4+2][lr+64] = b1v.z; Bs[lk4+3][lr+64] = b1v.w;
        __syncthreads();

        if (k0 + 16 < D_) {
            a0v = *(const float4*)(Ap0 + k0 + 16);
            a1v = *(const float4*)(Ap1 + k0 + 16);
            b0v = *(const float4*)(Bp0 + k0 + 16);
            b1v = *(const float4*)(Bp1 + k0 + 16);
        }

#pragma unroll
        for (int kk = 0; kk < 16; kk++) {
            float4 x0 = *(const float4*)&As[kk][rm];
            float4 x1 = *(const float4*)&As[kk][rm + 4];
            ulonglong2 yb0 = *(const ulonglong2*)&Bs[kk][cn];
            ulonglong2 yb1 = *(const ulonglong2*)&Bs[kk][cn + 4];
            uint64_t bp0 = yb0.x, bp1 = yb0.y, bp2 = yb1.x, bp3 = yb1.y;
            float av[8] = {x0.x, x0.y, x0.z, x0.w, x1.x, x1.y, x1.z, x1.w};
#pragma unroll
            for (int i = 0; i < 8; i++) {
                uint64_t s = splat2(av[i]);
                ffma2(accp[i][0], s, bp0);
                ffma2(accp[i][1], s, bp1);
                ffma2(accp[i][2], s, bp2);
                ffma2(accp[i][3], s, bp3);
            }
        }
        __syncthreads();
    }

#pragma unroll
    for (int i = 0; i < 8; i++) {
        int mm = m0 + rm + i;
        float4 e0 = *(const float4*)&d_enc_pre[(mm & 31) * G4 + n0 + cn];
        float4 e1 = *(const float4*)&d_enc_pre[(mm & 31) * G4 + n0 + cn + 4];
        float2 p0 = unpack2(accp[i][0]);
        float2 p1 = unpack2(accp[i][1]);
        float2 p2 = unpack2(accp[i][2]);
        float2 p3 = unpack2(accp[i][3]);
        float4 r0 = { p0.x + e0.x, p0.y + e0.y, p1.x + e0.z, p1.y + e0.w };
        float4 r1 = { p2.x + e1.x, p2.y + e1.y, p3.x + e1.z, p3.y + e1.w };
        *(float4*)&d_pre[(size_t)mm * G4 + n0 + cn]     = r0;
        *(float4*)&d_pre[(size_t)mm * G4 + n0 + cn + 4] = r1;
    }
}

// ---------------- persistent recurrence v4: mma.sync gates GEMM ------------
// Block owns 32 gate cols (4 gates x 8 h). gates[32,32] = hx[32,1024] @ Wslice^T,
// bf16 hi/lo split: Ah*Bh + Ah*Bl + Al*Bh (+pre). 16 warps = K-split(8) x M-split(2).
// Bh fragments persist in registers; Bl resident in smem; A staged per step.
__global__ __launch_bounds__(512, 1) void rec_mma()
{
    extern __shared__ __align__(16) __nv_bfloat16 sm[];
    __nv_bfloat16* sA  = sm;               // [32][PA]  staged A (Ah then Al)
    __nv_bfloat16* sBl = sm + 32 * PA;     // [32][PA]  W_hh lo slice (resident)
    float* red = (float*)(sm + 64 * PA);   // [2][8][16][32] fp32 partials (32KB)

    int tid = threadIdx.x, lane = tid & 31, w = tid >> 5;
    int ks = w >> 1, ms = w & 1;
    int hbase = blockIdx.x * 8;
    uint32_t sA_u  = smem_u32(sA);
    uint32_t sBl_u = smem_u32(sBl);

    // ldsm lane addressing (byte offsets; row stride = PA*2 = 2064 B)
    int a_off = (ms * 16 + (lane & 15)) * 2064 + ((lane >> 4) * 8) * 2;
    int b_row = ((lane >> 4) & 1) * 8 + (lane & 7);
    int b_off0 = b_row * 2064 + (((lane >> 3) & 1) * 8) * 2;          // np=0
    int b_off1 = (b_row + 16) * 2064 + (((lane >> 3) & 1) * 8) * 2;   // np=1
    int kbase = ks * 128;                  // element base of warp's k-chunk

    // ---- init: stage Bh slice into sA, Bl slice into sBl ----
#pragma unroll
    for (int i = 0; i < 8; i++) {
        int ch = tid + i * 512;            // 4096 chunks of 16B
        int row = ch >> 7, co = ch & 127;
        int jc = (row >> 3) * H_ + hbase + (row & 7);
        cp_async16(sA_u  + row * 2064 + co * 16, d_Wh + (size_t)jc * H_ + co * 8);
        cp_async16(sBl_u + row * 2064 + co * 16, d_Wl + (size_t)jc * H_ + co * 8);
    }
    CP_COMMIT(); CP_WAIT0();
    __syncthreads();

    // Bh fragments -> registers (8 k16 x [b0..b3 np0, b0..b3 np1])
    uint32_t bh[8][8];
#pragma unroll
    for (int kk = 0; kk < 8; kk++) {
        int cb = (kbase + kk * 16) * 2;
        ldsm_x4(bh[kk][0], bh[kk][1], bh[kk][2], bh[kk][3], sA_u + b_off0 + cb);
        ldsm_x4(bh[kk][4], bh[kk][5], bh[kk][6], bh[kk][7], sA_u + b_off1 + cb);
    }
    __syncthreads();   // sA free for A staging

    int b_own = tid >> 3, hh_own = tid & 7;   // cell mapping (tid<256)
    int hcol_own = hbase + hh_own;
    float creg = 0.f;

    for (int t = 0; t < T_; t++) {
        float p0 = 0.f, p1 = 0.f, p2 = 0.f, p3 = 0.f;
        if (tid < 256) {
            const float* pp = d_pre + ((size_t)(t * B_ + b_own)) * G4 + hcol_own;
            p0 = __ldg(pp);            p1 = __ldg(pp + H_);
            p2 = __ldg(pp + 2 * H_);   p3 = __ldg(pp + 3 * H_);
        }

        if (t > 0) {
            // ---- stage Ah (hx hi of step t-1) ----
            const __nv_bfloat16* Asrc = d_Ah + (size_t)(t - 1) * (B_ * H_);
#pragma unroll
            for (int i = 0; i < 8; i++) {
                int ch = tid + i * 512;
                int row = ch >> 7, co = ch & 127;
                cp_async16(sA_u + row * 2064 + co * 16, Asrc + row * H_ + co * 8);
            }
            CP_COMMIT(); CP_WAIT0();
            __syncthreads();

            float acc[4][4];
#pragma unroll
            for (int ni = 0; ni < 4; ni++)
#pragma unroll
                for (int q = 0; q < 4; q++) acc[ni][q] = 0.f;

            // seg0: Ah x Bh(regs); seg2: Ah x Bl(ldsm)
#pragma unroll
            for (int kk = 0; kk < 8; kk++) {
                int cb = (kbase + kk * 16) * 2;
                uint32_t a0, a1, a2, a3;
                ldsm_x4(a0, a1, a2, a3, sA_u + a_off + cb);
                mma16816(acc[0], a0, a1, a2, a3, bh[kk][0], bh[kk][1]);
                mma16816(acc[1], a0, a1, a2, a3, bh[kk][2], bh[kk][3]);
                mma16816(acc[2], a0, a1, a2, a3, bh[kk][4], bh[kk][5]);
                mma16816(acc[3], a0, a1, a2, a3, bh[kk][6], bh[kk][7]);
                uint32_t c0, c1, c2, c3, c4, c5, c6, c7;
                ldsm_x4(c0, c1, c2, c3, sBl_u + b_off0 + cb);
                ldsm_x4(c4, c5, c6, c7, sBl_u + b_off1 + cb);
                mma16816(acc[0], a0, a1, a2, a3, c0, c1);
                mma16816(acc[1], a0, a1, a2, a3, c2, c3);
                mma16816(acc[2], a0, a1, a2, a3, c4, c5);
                mma16816(acc[3], a0, a1, a2, a3, c6, c7);
            }

            // ---- restage Al, seg1: Al x Bh(regs) ----
            __syncthreads();
            const __nv_bfloat16* Asrc2 = d_Al + (size_t)(t - 1) * (B_ * H_);
#pragma unroll
            for (int i = 0; i < 8; i++) {
                int ch = tid + i * 512;
                int row = ch >> 7, co = ch & 127;
                cp_async16(sA_u + row * 2064 + co * 16, Asrc2 + row * H_ + co * 8);
            }
            CP_COMMIT(); CP_WAIT0();
            __syncthreads();
#pragma unroll
            for (int kk = 0; kk < 8; kk++) {
                int cb = (kbase + kk * 16) * 2;
                uint32_t a0, a1, a2, a3;
                ldsm_x4(a0, a1, a2, a3, sA_u + a_off + cb);
                mma16816(acc[0], a0, a1, a2, a3, bh[kk][0], bh[kk][1]);
                mma16816(acc[1], a0, a1, a2, a3, bh[kk][2], bh[kk][3]);
                mma16816(acc[2], a0, a1, a2, a3, bh[kk][4], bh[kk][5]);
                mma16816(acc[3], a0, a1, a2, a3, bh[kk][6], bh[kk][7]);
            }

            // ---- store partials to red: [ms][ks][m16row][32col] ----
            float* rw = red + ((ms * 8 + ks) * 16) * 32;
#pragma unroll
            for (int ni = 0; ni < 4; ni++) {
                int col = ni * 8 + (lane & 3) * 2;
                int r0i = (lane >> 2);
                *(float2*)&rw[r0i * 32 + col]       = make_float2(acc[ni][0], acc[ni][1]);
                *(float2*)&rw[(r0i + 8) * 32 + col] = make_float2(acc[ni][2], acc[ni][3]);
            }
            __syncthreads();
        }

        // ---- cell update (tid<256: thread = (b_own, hcol_own)) ----
        if (tid < 256) {
            float gi = 0.f, gf = 0.f, gg = 0.f, go = 0.f;
            if (t > 0) {
                int msb = b_own >> 4, mr = b_own & 15;
#pragma unroll
                for (int kq = 0; kq < 8; kq++) {
                    const float* r = red + (((msb * 8 + kq) * 16) + mr) * 32;
                    gi += r[hh_own];      gf += r[8  + hh_own];
                    gg += r[16 + hh_own]; go += r[24 + hh_own];
                }
            }
            gi += p0; gf += p1; gg += p2; go += p3;
            float si = 1.f / (1.f + expf(-gi));
            float sf = 1.f / (1.f + expf(-gf));
            float so = 1.f / (1.f + expf(-go));
            creg = sf * creg + si * tanhf(gg);
            float hn = so * tanhf(creg);
            __nv_bfloat16 ah = __float2bfloat16(hn);
            __nv_bfloat16 al = __float2bfloat16(hn - __bfloat162float(ah));
            size_t arow = (size_t)(t * B_ + b_own) * H_ + hcol_own;
            d_Ah[arow] = ah; d_Al[arow] = al;
        }

        // grid barrier: release/acquire, tid0 only
        __syncthreads();
        if (tid == 0) {
            asm volatile("red.release.gpu.global.add.u32 [%0], %1;"
                         :: "l"(&g_bar), "r"(1u) : "memory");
            unsigned target = 128u * (unsigned)(t + 1);
            unsigned v;
            do {
                asm volatile("ld.acquire.gpu.global.u32 %0, [%1];"
                             : "=r"(v) : "l"(&g_bar) : "memory");
            } while (v < target);
        }
        __syncthreads();
    }
}

// ---------------- tensor logits via mma.sync (bf16 hi/lo split) -----------
// At the fallback-HMMA ceiling: inner loop untouched (r10/r12-proven).
#define PAD_ 40
__global__ __launch_bounds__(256, 2) void logits_mma(
    const float* __restrict__ bfc, float* __restrict__ out)
{
    __shared__ __align__(16) __nv_bfloat16 sA[2][128 * PAD_];
    __shared__ __align__(16) __nv_bfloat16 sB[2][128 * PAD_];

    int tid = threadIdx.x, lane = tid & 31, w = tid >> 5;
    int wm = w & 3, wn = w >> 2;
    int m0 = blockIdx.x * 128, n0 = blockIdx.y * 128;

    float c[2][8][4];
#pragma unroll
    for (int mi = 0; mi < 2; mi++)
#pragma unroll
        for (int ni = 0; ni < 8; ni++)
#pragma unroll
            for (int q = 0; q < 4; q++) c[mi][ni][q] = 0.f;

    int lrow = tid >> 2, lch = (tid & 3) * 8;

    uint4 pa[2], pb[2];
    {
#pragma unroll
        for (int i = 0; i < 2; i++) {
            int row = lrow + i * 64;
            pa[i] = *(const uint4*)(d_Ah + (size_t)(m0 + row) * H_ + lch);
            pb[i] = *(const uint4*)(d_Bh + (size_t)(n0 + row) * H_ + lch);
        }
    }

    int a_col_l = (lane >> 4) * 8;
    int b_row_l = wn * 64 + ((lane >> 4) & 1) * 8 + (lane & 7);
    int b_col_l = ((lane >> 3) & 1) * 8;

    int buf = 0;
    for (int it = 0; it < 96; it++) {
#pragma unroll
        for (int i = 0; i < 2; i++) {
            int row = lrow + i * 64;
            *(uint4*)(&sA[buf][row * PAD_ + lch]) = pa[i];
            *(uint4*)(&sB[buf][row * PAD_ + lch]) = pb[i];
        }
        __syncthreads();

        if (it + 1 < 96) {
            int nit = it + 1;
            int seg = nit >> 5;
            int k0  = (nit & 31) * 32;
            const __nv_bfloat16* As = (seg == 1) ? d_Al : d_Ah;
            const __nv_bfloat16* Bs = (seg == 2) ? d_Bl : d_Bh;
#pragma unroll
            for (int i = 0; i < 2; i++) {
                int row = lrow + i * 64;
                pa[i] = *(const uint4*)(As + (size_t)(m0 + row) * H_ + k0 + lch);
                pb[i] = *(const uint4*)(Bs + (size_t)(n0 + row) * H_ + k0 + lch);
            }
        }

#pragma unroll
        for (int ks = 0; ks < 2; ks++) {
            uint32_t af[2][4];
#pragma unroll
            for (int mi = 0; mi < 2; mi++) {
                int row = wm * 32 + mi * 16 + (lane & 15);
                uint32_t a = smem_u32(&sA[buf][row * PAD_ + ks * 16 + a_col_l]);
                ldsm_x4(af[mi][0], af[mi][1], af[mi][2], af[mi][3], a);
            }
#pragma unroll
            for (int np = 0; np < 4; np++) {
                uint32_t b0, b1, b2, b3;
                uint32_t ba = smem_u32(
                    &sB[buf][(b_row_l + np * 16) * PAD_ + ks * 16 + b_col_l]);
                ldsm_x4(b0, b1, b2, b3, ba);
#pragma unroll
                for (int mi = 0; mi < 2; mi++) {
                    mma16816(c[mi][np * 2],     af[mi][0], af[mi][1], af[mi][2], af[mi][3], b0, b1);
                    mma16816(c[mi][np * 2 + 1], af[mi][0], af[mi][1], af[mi][2], af[mi][3], b2, b3);
                }
            }
        }
        buf ^= 1;
    }

    // epilogue: store + fused per-row argmax via packed atomicMax
#pragma unroll
    for (int mi = 0; mi < 2; mi++) {
        unsigned long long key0 = 0ull, key1 = 0ull;
        int rbase = m0 + wm * 32 + mi * 16 + (lane >> 2);
#pragma unroll
        for (int ni = 0; ni < 8; ni++) {
            int col = n0 + wn * 64 + ni * 8 + (lane & 3) * 2;
            float2 bb = *(const float2*)&bfc[col];
            float2 r0 = { c[mi][ni][0] + bb.x, c[mi][ni][1] + bb.y };
            float2 r1 = { c[mi][ni][2] + bb.x, c[mi][ni][3] + bb.y };
            *(float2*)&out[(size_t)rbase * V_ + col]       = r0;
            *(float2*)&out[(size_t)(rbase + 8) * V_ + col] = r1;
            unsigned long long k;
            k = ((unsigned long long)fmono(r0.x) << 32) | (uint32_t)~col;
            if (k > key0) key0 = k;
            k = ((unsigned long long)fmono(r0.y) << 32) | (uint32_t)~(col + 1);
            if (k > key0) key0 = k;
            k = ((unsigned long long)fmono(r1.x) << 32) | (uint32_t)~col;
            if (k > key1) key1 = k;
            k = ((unsigned long long)fmono(r1.y) << 32) | (uint32_t)~(col + 1);
            if (k > key1) key1 = k;
        }
#pragma unroll
        for (int s = 1; s < 4; s <<= 1) {
            unsigned long long o0 = __shfl_xor_sync(0xFFFFFFFFu, key0, s);
            unsigned long long o1 = __shfl_xor_sync(0xFFFFFFFFu, key1, s);
            if (o0 > key0) key0 = o0;
            if (o1 > key1) key1 = o1;
        }
        if ((lane & 3) == 0) {
            atomicMax(&d_amax[rbase], key0);
            atomicMax(&d_amax[rbase + 8], key1);
        }
    }
}

// ---------------- finalize predic from packed argmax ----------------------
__global__ __launch_bounds__(256) void pred_finalize(float* __restrict__ pred)
{
    int m = blockIdx.x * 256 + threadIdx.x;
    if (m >= TB) return;
    unsigned col = ~(unsigned)(d_amax[m] & 0xFFFFFFFFull);
    int t = m >> 5, b = m & 31;
    pred[b * T_ + t] = (float)col;
}

// ------------------------------------------------------------------------
extern "C" void kernel_launch(void* const* d_in, const int* in_sizes, int n_in,
                              void* d_out, int out_size)
{
    const float* encoder = (const float*)d_in[0];
    const int*   gtruths = (const int*)  d_in[1];
    const float* emb     = (const float*)d_in[2];
    const float* W_ih    = (const float*)d_in[3];
    const float* W_hh    = (const float*)d_in[4];
    const float* b_ih    = (const float*)d_in[5];
    const float* b_hh    = (const float*)d_in[6];
    const float* W_fc    = (const float*)d_in[7];
    const float* b_fc    = (const float*)d_in[8];
    float* out = (float*)d_out;

    const int REC_SMEM = 64 * PA * 2 + 2 * 8 * 16 * 32 * 4;   // 164864 B

    static int attr_set = 0;
    if (!attr_set) {
        cudaFuncSetAttribute(rec_mma,
                             cudaFuncAttributeMaxDynamicSharedMemorySize, REC_SMEM);
        attr_set = 1;
    }

    conv_wfc<<<(int)(((size_t)V_ * H_ / 4) / 256), 256>>>(W_fc);
    conv_whh<<<(G4 * H_ / 4) / 256, 256>>>(W_hh);
    enc_pre_kernel<<<G4 / 32, 256>>>(encoder, W_ih, b_ih, b_hh);
    pre_gemm_big<<<dim3(TB / 128, G4 / 128), 256>>>(emb, gtruths, W_ih);
    rec_mma<<<128, 512, REC_SMEM>>>();
    logits_mma<<<dim3(TB / 128, V_ / 128), 256>>>(b_fc, out);
    if (out_size >= TB * V_ + TB)
        pred_finalize<<<(TB + 255) / 256, 256>>>(out + (size_t)TB * V_);
}

// round 16
// speedup vs baseline: 1.2961x; 1.0658x over previous
#include <cuda_runtime.h>
#include <cuda_bf16.h>
#include <math.h>
#include <stdint.h>

#define B_  32
#define T_  64
#define V_  32000
#define D_  512
#define E_  1024
#define H_  1024
#define G4  4096      // 4*H
#define TB  2048      // T*B
#define PA  1032      // padded row stride (bf16 elems) for rec smem tiles

// ---------------- device scratch (no allocations allowed) ----------------
__device__ float d_enc_pre[B_ * G4];                  // 0.5 MB
__device__ float d_pre[TB * G4];                      // 32 MB
__device__ unsigned g_bar;
__device__ __nv_bfloat16 d_Ah[TB * H_];               // 4 MB  hx hi
__device__ __nv_bfloat16 d_Al[TB * H_];               // 4 MB  hx lo
__device__ __nv_bfloat16 d_Bh[(size_t)V_ * H_];       // 64 MB W_fc hi
__device__ __nv_bfloat16 d_Bl[(size_t)V_ * H_];       // 64 MB W_fc lo
__device__ __nv_bfloat16 d_Wh[G4 * H_];               // 8 MB  W_hh hi
__device__ __nv_bfloat16 d_Wl[G4 * H_];               // 8 MB  W_hh lo
__device__ __nv_bfloat16 d_pAh[TB * D_];              // 2 MB  gathered emb hi
__device__ __nv_bfloat16 d_pAl[TB * D_];              // 2 MB  gathered emb lo
__device__ __nv_bfloat16 d_Wih_h[G4 * D_];            // 4 MB  W_ih[:,E:] hi
__device__ __nv_bfloat16 d_Wih_l[G4 * D_];            // 4 MB  W_ih[:,E:] lo
__device__ unsigned long long d_amax[TB];             // packed (val, ~col)

// ======================= PTX helpers (base-target, no 'a' features) ======
__device__ __forceinline__ uint32_t smem_u32(const void* p) {
    uint32_t a;
    asm("{ .reg .u64 t; cvta.to.shared.u64 t, %1; cvt.u32.u64 %0, t; }"
        : "=r"(a) : "l"(p));
    return a;
}
__device__ __forceinline__ void ldsm_x4(uint32_t& r0, uint32_t& r1,
                                        uint32_t& r2, uint32_t& r3, uint32_t a) {
    asm volatile("ldmatrix.sync.aligned.m8n8.x4.shared.b16 {%0,%1,%2,%3}, [%4];"
                 : "=r"(r0), "=r"(r1), "=r"(r2), "=r"(r3) : "r"(a));
}
__device__ __forceinline__ void mma16816(float* c,
    uint32_t a0, uint32_t a1, uint32_t a2, uint32_t a3, uint32_t b0, uint32_t b1) {
    asm volatile("mma.sync.aligned.m16n8k16.row.col.f32.bf16.bf16.f32 "
                 "{%0,%1,%2,%3}, {%4,%5,%6,%7}, {%8,%9}, {%0,%1,%2,%3};"
                 : "+f"(c[0]), "+f"(c[1]), "+f"(c[2]), "+f"(c[3])
                 : "r"(a0), "r"(a1), "r"(a2), "r"(a3), "r"(b0), "r"(b1));
}
__device__ __forceinline__ void cp_async16(uint32_t saddr, const void* gptr) {
    asm volatile("cp.async.cg.shared.global [%0], [%1], 16;"
                 :: "r"(saddr), "l"(gptr));
}
#define CP_COMMIT() asm volatile("cp.async.commit_group;" ::: "memory")
#define CP_WAIT0()  asm volatile("cp.async.wait_group 0;" ::: "memory")
// monotone float->uint (order-preserving)
__device__ __forceinline__ uint32_t fmono(float f) {
    uint32_t u = __float_as_uint(f);
    return (u & 0x80000000u) ? ~u : (u | 0x80000000u);
}
// fp32 -> (hi, lo) bf16 pair
__device__ __forceinline__ void bsplit(float v, __nv_bfloat16& h, __nv_bfloat16& l) {
    h = __float2bfloat16(v);
    l = __float2bfloat16(v - __bfloat162float(h));
}
struct bf4 { __nv_bfloat16 a, b, c, d; };

// ---------------- W_fc fp32 -> (hi, lo) bf16 split -----------------------
__global__ __launch_bounds__(256) void conv_wfc(const float* __restrict__ W)
{
    size_t i = (size_t)blockIdx.x * 256 + threadIdx.x;
    float4 v = ((const float4*)W)[i];
    bf4 h, l;
    bsplit(v.x, h.a, l.a); bsplit(v.y, h.b, l.b);
    bsplit(v.z, h.c, l.c); bsplit(v.w, h.d, l.d);
    *(bf4*)(d_Bh + 4 * i) = h;
    *(bf4*)(d_Bl + 4 * i) = l;
}

// ---------------- W_hh fp32 -> (hi, lo) bf16 split -----------------------
__global__ __launch_bounds__(256) void conv_whh(const float* __restrict__ W)
{
    size_t i = (size_t)blockIdx.x * 256 + threadIdx.x;
    float4 v = ((const float4*)W)[i];
    bf4 h, l;
    bsplit(v.x, h.a, l.a); bsplit(v.y, h.b, l.b);
    bsplit(v.z, h.c, l.c); bsplit(v.w, h.d, l.d);
    *(bf4*)(d_Wh + 4 * i) = h;
    *(bf4*)(d_Wl + 4 * i) = l;
}

// ---------------- W_ih[:, E:] fp32 -> (hi, lo) bf16 split -----------------
__global__ __launch_bounds__(256) void conv_wih(const float* __restrict__ Wih)
{
    int idx = blockIdx.x * 256 + threadIdx.x;      // float4 index over [4096,512]
    int j = idx >> 7, ci = idx & 127;
    float4 v = *(const float4*)(Wih + (size_t)j * (E_ + D_) + E_ + ci * 4);
    bf4 h, l;
    bsplit(v.x, h.a, l.a); bsplit(v.y, h.b, l.b);
    bsplit(v.z, h.c, l.c); bsplit(v.w, h.d, l.d);
    *(bf4*)(d_Wih_h + (size_t)j * D_ + ci * 4) = h;
    *(bf4*)(d_Wih_l + (size_t)j * D_ + ci * 4) = l;
}

// ---------------- gathered emb rows -> (hi, lo) bf16 ----------------------
__global__ __launch_bounds__(128) void conv_emb(
    const float* __restrict__ emb, const int* __restrict__ gt)
{
    int m = blockIdx.x;                            // m = t*B + b
    int tok = gt[(m & 31) * T_ + (m >> 5)];
    int i = threadIdx.x;                           // 128 float4 per row
    float4 v = *(const float4*)(emb + (size_t)tok * D_ + i * 4);
    bf4 h, l;
    bsplit(v.x, h.a, l.a); bsplit(v.y, h.b, l.b);
    bsplit(v.z, h.c, l.c); bsplit(v.w, h.d, l.d);
    *(bf4*)(d_pAh + (size_t)m * D_ + i * 4) = h;
    *(bf4*)(d_pAl + (size_t)m * D_ + i * 4) = l;
}

// ---------------- enc_pre + replay-state init (fused) ---------------------
__global__ __launch_bounds__(256) void enc_pre_kernel(
    const float* __restrict__ enc, const float* __restrict__ Wih,
    const float* __restrict__ bih, const float* __restrict__ bhh)
{
    int tid = threadIdx.x;
    int gidx = blockIdx.x * 256 + tid;
    if (gidx < TB) d_amax[gidx] = 0ull;
    if (gidx == 0) g_bar = 0u;

    __shared__ float As[32][36];
    __shared__ float Bs[32][36];
    int j0  = blockIdx.x * 32;
    int lr  = tid >> 3, lk = (tid & 7) * 4;
    int col = tid & 31, rg = (tid >> 5) * 4;
    float acc[4] = {0.f, 0.f, 0.f, 0.f};

    for (int k0 = 0; k0 < E_; k0 += 32) {
        float4 av = *(const float4*)(enc + lr * E_ + k0 + lk);
        float4 bv = *(const float4*)(Wih + (size_t)(j0 + lr) * (E_ + D_) + k0 + lk);
        As[lk+0][lr] = av.x; As[lk+1][lr] = av.y; As[lk+2][lr] = av.z; As[lk+3][lr] = av.w;
        Bs[lk+0][lr] = bv.x; Bs[lk+1][lr] = bv.y; Bs[lk+2][lr] = bv.z; Bs[lk+3][lr] = bv.w;
        __syncthreads();
#pragma unroll
        for (int kk = 0; kk < 32; kk++) {
            float4 a = *(const float4*)&As[kk][rg];
            float  b = Bs[kk][col];
            acc[0] += a.x * b; acc[1] += a.y * b; acc[2] += a.z * b; acc[3] += a.w * b;
        }
        __syncthreads();
    }
    float bias = bih[j0 + col] + bhh[j0 + col];
#pragma unroll
    for (int i = 0; i < 4; i++)
        d_enc_pre[(rg + i) * G4 + j0 + col] = acc[i] + bias;
}

// ---------------- pre = emb_split @ Wih_split^T + enc_pre (mma.sync) ------
// Same skeleton as logits_mma: CTA 128x128, 8 warps (4m x 2n), BK=32,
// double buffer, reg prefetch. K=512 per segment, 3 segments = 48 iters.
#define PAD_ 40
__global__ __launch_bounds__(256, 2) void pre_mma()
{
    __shared__ __align__(16) __nv_bfloat16 sA[2][128 * PAD_];
    __shared__ __align__(16) __nv_bfloat16 sB[2][128 * PAD_];

    int tid = threadIdx.x, lane = tid & 31, w = tid >> 5;
    int wm = w & 3, wn = w >> 2;
    int m0 = blockIdx.x * 128, n0 = blockIdx.y * 128;

    float c[2][8][4];
#pragma unroll
    for (int mi = 0; mi < 2; mi++)
#pragma unroll
        for (int ni = 0; ni < 8; ni++)
#pragma unroll
            for (int q = 0; q < 4; q++) c[mi][ni][q] = 0.f;

    int lrow = tid >> 2, lch = (tid & 3) * 8;

    uint4 pa[2], pb[2];
#pragma unroll
    for (int i = 0; i < 2; i++) {
        int row = lrow + i * 64;
        pa[i] = *(const uint4*)(d_pAh   + (size_t)(m0 + row) * D_ + lch);
        pb[i] = *(const uint4*)(d_Wih_h + (size_t)(n0 + row) * D_ + lch);
    }

    int a_col_l = (lane >> 4) * 8;
    int b_row_l = wn * 64 + ((lane >> 4) & 1) * 8 + (lane & 7);
    int b_col_l = ((lane >> 3) & 1) * 8;

    int buf = 0;
    for (int it = 0; it < 48; it++) {
#pragma unroll
        for (int i = 0; i < 2; i++) {
            int row = lrow + i * 64;
            *(uint4*)(&sA[buf][row * PAD_ + lch]) = pa[i];
            *(uint4*)(&sB[buf][row * PAD_ + lch]) = pb[i];
        }
        __syncthreads();

        if (it + 1 < 48) {
            int nit = it + 1;
            int seg = nit >> 4;                 // 0..2
            int k0  = (nit & 15) * 32;
            const __nv_bfloat16* As = (seg == 1) ? d_pAl   : d_pAh;
            const __nv_bfloat16* Bs = (seg == 2) ? d_Wih_l : d_Wih_h;
#pragma unroll
            for (int i = 0; i < 2; i++) {
                int row = lrow + i * 64;
                pa[i] = *(const uint4*)(As + (size_t)(m0 + row) * D_ + k0 + lch);
                pb[i] = *(const uint4*)(Bs + (size_t)(n0 + row) * D_ + k0 + lch);
            }
        }

#pragma unroll
        for (int ks = 0; ks < 2; ks++) {
            uint32_t af[2][4];
#pragma unroll
            for (int mi = 0; mi < 2; mi++) {
                int row = wm * 32 + mi * 16 + (lane & 15);
                uint32_t a = smem_u32(&sA[buf][row * PAD_ + ks * 16 + a_col_l]);
                ldsm_x4(af[mi][0], af[mi][1], af[mi][2], af[mi][3], a);
            }
#pragma unroll
            for (int np = 0; np < 4; np++) {
                uint32_t b0, b1, b2, b3;
                uint32_t ba = smem_u32(
                    &sB[buf][(b_row_l + np * 16) * PAD_ + ks * 16 + b_col_l]);
                ldsm_x4(b0, b1, b2, b3, ba);
#pragma unroll
                for (int mi = 0; mi < 2; mi++) {
                    mma16816(c[mi][np * 2],     af[mi][0], af[mi][1], af[mi][2], af[mi][3], b0, b1);
                    mma16816(c[mi][np * 2 + 1], af[mi][0], af[mi][1], af[mi][2], af[mi][3], b2, b3);
                }
            }
        }
        buf ^= 1;
    }

    // epilogue: d_pre = acc + enc_pre[b]  (b = row & 31)
#pragma unroll
    for (int mi = 0; mi < 2; mi++) {
#pragma unroll
        for (int ni = 0; ni < 8; ni++) {
            int row = m0 + wm * 32 + mi * 16 + (lane >> 2);
            int col = n0 + wn * 64 + ni * 8 + (lane & 3) * 2;
            float2 e0 = *(const float2*)&d_enc_pre[(row & 31) * G4 + col];
            float2 e1 = *(const float2*)&d_enc_pre[((row + 8) & 31) * G4 + col];
            float2 r0 = { c[mi][ni][0] + e0.x, c[mi][ni][1] + e0.y };
            float2 r1 = { c[mi][ni][2] + e1.x, c[mi][ni][3] + e1.y };
            *(float2*)&d_pre[(size_t)row * G4 + col]       = r0;
            *(float2*)&d_pre[(size_t)(row + 8) * G4 + col] = r1;
        }
    }
}

// ---------------- persistent recurrence v5: mma.sync, single-stage --------
// Block owns 32 gate cols. Ah and Al staged together (one cp.async wait);
// red overlays sAl (free after MMA reads). 16 warps = K-split(8) x M-split(2).
__global__ __launch_bounds__(512, 1) void rec_mma()
{
    extern __shared__ __align__(16) __nv_bfloat16 sm[];
    __nv_bfloat16* sAh = sm;               // [32][PA] staged Ah (Wh at init)
    __nv_bfloat16* sAl = sm + 32 * PA;     // [32][PA] staged Al
    __nv_bfloat16* sBl = sm + 64 * PA;     // [32][PA] W_hh lo slice (resident)
    float* red = (float*)(sm + 32 * PA);   // overlays sAl after MMA reads

    int tid = threadIdx.x, lane = tid & 31, w = tid >> 5;
    int ks = w >> 1, ms = w & 1;
    int hbase = blockIdx.x * 8;
    uint32_t sAh_u = smem_u32(sAh);
    uint32_t sAl_u = smem_u32(sAl);
    uint32_t sBl_u = smem_u32(sBl);

    int a_off = (ms * 16 + (lane & 15)) * 2064 + ((lane >> 4) * 8) * 2;
    int b_row = ((lane >> 4) & 1) * 8 + (lane & 7);
    int b_off0 = b_row * 2064 + (((lane >> 3) & 1) * 8) * 2;
    int b_off1 = (b_row + 16) * 2064 + (((lane >> 3) & 1) * 8) * 2;
    int kbase = ks * 128;

    // ---- init: stage Wh into sAh, Wl into sBl ----
#pragma unroll
    for (int i = 0; i < 8; i++) {
        int ch = tid + i * 512;
        int row = ch >> 7, co = ch & 127;
        int jc = (row >> 3) * H_ + hbase + (row & 7);
        cp_async16(sAh_u + row * 2064 + co * 16, d_Wh + (size_t)jc * H_ + co * 8);
        cp_async16(sBl_u + row * 2064 + co * 16, d_Wl + (size_t)jc * H_ + co * 8);
    }
    CP_COMMIT(); CP_WAIT0();
    __syncthreads();

    uint32_t bh[8][8];
#pragma unroll
    for (int kk = 0; kk < 8; kk++) {
        int cb = (kbase + kk * 16) * 2;
        ldsm_x4(bh[kk][0], bh[kk][1], bh[kk][2], bh[kk][3], sAh_u + b_off0 + cb);
        ldsm_x4(bh[kk][4], bh[kk][5], bh[kk][6], bh[kk][7], sAh_u + b_off1 + cb);
    }
    __syncthreads();

    int b_own = tid >> 3, hh_own = tid & 7;
    int hcol_own = hbase + hh_own;
    float creg = 0.f;

    for (int t = 0; t < T_; t++) {
        float p0 = 0.f, p1 = 0.f, p2 = 0.f, p3 = 0.f;
        if (tid < 256) {
            const float* pp = d_pre + ((size_t)(t * B_ + b_own)) * G4 + hcol_own;
            p0 = __ldg(pp);            p1 = __ldg(pp + H_);
            p2 = __ldg(pp + 2 * H_);   p3 = __ldg(pp + 3 * H_);
        }

        if (t > 0) {
            // ---- stage Ah and Al together (one wait) ----
            const __nv_bfloat16* Ah_src = d_Ah + (size_t)(t - 1) * (B_ * H_);
            const __nv_bfloat16* Al_src = d_Al + (size_t)(t - 1) * (B_ * H_);
#pragma unroll
            for (int i = 0; i < 8; i++) {
                int ch = tid + i * 512;
                int row = ch >> 7, co = ch & 127;
                cp_async16(sAh_u + row * 2064 + co * 16, Ah_src + row * H_ + co * 8);
                cp_async16(sAl_u + row * 2064 + co * 16, Al_src + row * H_ + co * 8);
            }
            CP_COMMIT(); CP_WAIT0();
            __syncthreads();

            float acc[4][4];
#pragma unroll
            for (int ni = 0; ni < 4; ni++)
#pragma unroll
                for (int q = 0; q < 4; q++) acc[ni][q] = 0.f;

            // 12 MMA per kk: Ah*Bh, Ah*Bl, Al*Bh
#pragma unroll
            for (int kk = 0; kk < 8; kk++) {
                int cb = (kbase + kk * 16) * 2;
                uint32_t a0, a1, a2, a3, l0, l1, l2, l3;
                ldsm_x4(a0, a1, a2, a3, sAh_u + a_off + cb);
                ldsm_x4(l0, l1, l2, l3, sAl_u + a_off + cb);
                mma16816(acc[0], a0, a1, a2, a3, bh[kk][0], bh[kk][1]);
                mma16816(acc[1], a0, a1, a2, a3, bh[kk][2], bh[kk][3]);
                mma16816(acc[2], a0, a1, a2, a3, bh[kk][4], bh[kk][5]);
                mma16816(acc[3], a0, a1, a2, a3, bh[kk][6], bh[kk][7]);
                uint32_t c0, c1, c2, c3, c4, c5, c6, c7;
                ldsm_x4(c0, c1, c2, c3, sBl_u + b_off0 + cb);
                ldsm_x4(c4, c5, c6, c7, sBl_u + b_off1 + cb);
                mma16816(acc[0], a0, a1, a2, a3, c0, c1);
                mma16816(acc[1], a0, a1, a2, a3, c2, c3);
                mma16816(acc[2], a0, a1, a2, a3, c4, c5);
                mma16816(acc[3], a0, a1, a2, a3, c6, c7);
                mma16816(acc[0], l0, l1, l2, l3, bh[kk][0], bh[kk][1]);
                mma16816(acc[1], l0, l1, l2, l3, bh[kk][2], bh[kk][3]);
                mma16816(acc[2], l0, l1, l2, l3, bh[kk][4], bh[kk][5]);
                mma16816(acc[3], l0, l1, l2, l3, bh[kk][6], bh[kk][7]);
            }
            __syncthreads();   // all sAl reads done before red overlay write

            // ---- store partials: red[ms][ks][m16row][32col] (on sAl) ----
            float* rw = red + ((ms * 8 + ks) * 16) * 32;
#pragma unroll
            for (int ni = 0; ni < 4; ni++) {
                int col = ni * 8 + (lane & 3) * 2;
                int r0i = (lane >> 2);
                *(float2*)&rw[r0i * 32 + col]       = make_float2(acc[ni][0], acc[ni][1]);
                *(float2*)&rw[(r0i + 8) * 32 + col] = make_float2(acc[ni][2], acc[ni][3]);
            }
            __syncthreads();
        }

        // ---- cell update ----
        if (tid < 256) {
            float gi = 0.f, gf = 0.f, gg = 0.f, go = 0.f;
            if (t > 0) {
                int msb = b_own >> 4, mr = b_own & 15;
#pragma unroll
                for (int kq = 0; kq < 8; kq++) {
                    const float* r = red + (((msb * 8 + kq) * 16) + mr) * 32;
                    gi += r[hh_own];      gf += r[8  + hh_own];
                    gg += r[16 + hh_own]; go += r[24 + hh_own];
                }
            }
            gi += p0; gf += p1; gg += p2; go += p3;
            float si = 1.f / (1.f + expf(-gi));
            float sf = 1.f / (1.f + expf(-gf));
            float so = 1.f / (1.f + expf(-go));
            creg = sf * creg + si * tanhf(gg);
            float hn = so * tanhf(creg);
            __nv_bfloat16 ah = __float2bfloat16(hn);
            __nv_bfloat16 al = __float2bfloat16(hn - __bfloat162float(ah));
            size_t arow = (size_t)(t * B_ + b_own) * H_ + hcol_own;
            d_Ah[arow] = ah; d_Al[arow] = al;
        }

        // grid barrier: release/acquire, tid0 only
        __syncthreads();
        if (tid == 0) {
            asm volatile("red.release.gpu.global.add.u32 [%0], %1;"
                         :: "l"(&g_bar), "r"(1u) : "memory");
            unsigned target = 128u * (unsigned)(t + 1);
            unsigned v;
            do {
                asm volatile("ld.acquire.gpu.global.u32 %0, [%1];"
                             : "=r"(v) : "l"(&g_bar) : "memory");
            } while (v < target);
        }
        __syncthreads();
    }
}

// ---------------- tensor logits via mma.sync (bf16 hi/lo split) -----------
// At the fallback-HMMA ceiling: unchanged (r10/r12/r15-proven).
__global__ __launch_bounds__(256, 2) void logits_mma(
    const float* __restrict__ bfc, float* __restrict__ out)
{
    __shared__ __align__(16) __nv_bfloat16 sA[2][128 * PAD_];
    __shared__ __align__(16) __nv_bfloat16 sB[2][128 * PAD_];

    int tid = threadIdx.x, lane = tid & 31, w = tid >> 5;
    int wm = w & 3, wn = w >> 2;
    int m0 = blockIdx.x * 128, n0 = blockIdx.y * 128;

    float c[2][8][4];
#pragma unroll
    for (int mi = 0; mi < 2; mi++)
#pragma unroll
        for (int ni = 0; ni < 8; ni++)
#pragma unroll
            for (int q = 0; q < 4; q++) c[mi][ni][q] = 0.f;

    int lrow = tid >> 2, lch = (tid & 3) * 8;

    uint4 pa[2], pb[2];
    {
#pragma unroll
        for (int i = 0; i < 2; i++) {
            int row = lrow + i * 64;
            pa[i] = *(const uint4*)(d_Ah + (size_t)(m0 + row) * H_ + lch);
            pb[i] = *(const uint4*)(d_Bh + (size_t)(n0 + row) * H_ + lch);
        }
    }

    int a_col_l = (lane >> 4) * 8;
    int b_row_l = wn * 64 + ((lane >> 4) & 1) * 8 + (lane & 7);
    int b_col_l = ((lane >> 3) & 1) * 8;

    int buf = 0;
    for (int it = 0; it < 96; it++) {
#pragma unroll
        for (int i = 0; i < 2; i++) {
            int row = lrow + i * 64;
            *(uint4*)(&sA[buf][row * PAD_ + lch]) = pa[i];
            *(uint4*)(&sB[buf][row * PAD_ + lch]) = pb[i];
        }
        __syncthreads();

        if (it + 1 < 96) {
            int nit = it + 1;
            int seg = nit >> 5;
            int k0  = (nit & 31) * 32;
            const __nv_bfloat16* As = (seg == 1) ? d_Al : d_Ah;
            const __nv_bfloat16* Bs = (seg == 2) ? d_Bl : d_Bh;
#pragma unroll
            for (int i = 0; i < 2; i++) {
                int row = lrow + i * 64;
                pa[i] = *(const uint4*)(As + (size_t)(m0 + row) * H_ + k0 + lch);
                pb[i] = *(const uint4*)(Bs + (size_t)(n0 + row) * H_ + k0 + lch);
            }
        }

#pragma unroll
        for (int ks = 0; ks < 2; ks++) {
            uint32_t af[2][4];
#pragma unroll
            for (int mi = 0; mi < 2; mi++) {
                int row = wm * 32 + mi * 16 + (lane & 15);
                uint32_t a = smem_u32(&sA[buf][row * PAD_ + ks * 16 + a_col_l]);
                ldsm_x4(af[mi][0], af[mi][1], af[mi][2], af[mi][3], a);
            }
#pragma unroll
            for (int np = 0; np < 4; np++) {
                uint32_t b0, b1, b2, b3;
                uint32_t ba = smem_u32(
                    &sB[buf][(b_row_l + np * 16) * PAD_ + ks * 16 + b_col_l]);
                ldsm_x4(b0, b1, b2, b3, ba);
#pragma unroll
                for (int mi = 0; mi < 2; mi++) {
                    mma16816(c[mi][np * 2],     af[mi][0], af[mi][1], af[mi][2], af[mi][3], b0, b1);
                    mma16816(c[mi][np * 2 + 1], af[mi][0], af[mi][1], af[mi][2], af[mi][3], b2, b3);
                }
            }
        }
        buf ^= 1;
    }

    // epilogue: store + fused per-row argmax via packed atomicMax
#pragma unroll
    for (int mi = 0; mi < 2; mi++) {
        unsigned long long key0 = 0ull, key1 = 0ull;
        int rbase = m0 + wm * 32 + mi * 16 + (lane >> 2);
#pragma unroll
        for (int ni = 0; ni < 8; ni++) {
            int col = n0 + wn * 64 + ni * 8 + (lane & 3) * 2;
            float2 bb = *(const float2*)&bfc[col];
            float2 r0 = { c[mi][ni][0] + bb.x, c[mi][ni][1] + bb.y };
            float2 r1 = { c[mi][ni][2] + bb.x, c[mi][ni][3] + bb.y };
            *(float2*)&out[(size_t)rbase * V_ + col]       = r0;
            *(float2*)&out[(size_t)(rbase + 8) * V_ + col] = r1;
            unsigned long long k;
            k = ((unsigned long long)fmono(r0.x) << 32) | (uint32_t)~col;
            if (k > key0) key0 = k;
            k = ((unsigned long long)fmono(r0.y) << 32) | (uint32_t)~(col + 1);
            if (k > key0) key0 = k;
            k = ((unsigned long long)fmono(r1.x) << 32) | (uint32_t)~col;
            if (k > key1) key1 = k;
            k = ((unsigned long long)fmono(r1.y) << 32) | (uint32_t)~(col + 1);
            if (k > key1) key1 = k;
        }
#pragma unroll
        for (int s = 1; s < 4; s <<= 1) {
            unsigned long long o0 = __shfl_xor_sync(0xFFFFFFFFu, key0, s);
            unsigned long long o1 = __shfl_xor_sync(0xFFFFFFFFu, key1, s);
            if (o0 > key0) key0 = o0;
            if (o1 > key1) key1 = o1;
        }
        if ((lane & 3) == 0) {
            atomicMax(&d_amax[rbase], key0);
            atomicMax(&d_amax[rbase + 8], key1);
        }
    }
}

// ---------------- finalize predic from packed argmax ----------------------
__global__ __launch_bounds__(256) void pred_finalize(float* __restrict__ pred)
{
    int m = blockIdx.x * 256 + threadIdx.x;
    if (m >= TB) return;
    unsigned col = ~(unsigned)(d_amax[m] & 0xFFFFFFFFull);
    int t = m >> 5, b = m & 31;
    pred[b * T_ + t] = (float)col;
}

// ------------------------------------------------------------------------
extern "C" void kernel_launch(void* const* d_in, const int* in_sizes, int n_in,
                              void* d_out, int out_size)
{
    const float* encoder = (const float*)d_in[0];
    const int*   gtruths = (const int*)  d_in[1];
    const float* emb     = (const float*)d_in[2];
    const float* W_ih    = (const float*)d_in[3];
    const float* W_hh    = (const float*)d_in[4];
    const float* b_ih    = (const float*)d_in[5];
    const float* b_hh    = (const float*)d_in[6];
    const float* W_fc    = (const float*)d_in[7];
    const float* b_fc    = (const float*)d_in[8];
    float* out = (float*)d_out;

    const int REC_SMEM = 96 * PA * 2;   // 3 tiles (red overlays sAl): 198144 B

    static int attr_set = 0;
    if (!attr_set) {
        cudaFuncSetAttribute(rec_mma,
                             cudaFuncAttributeMaxDynamicSharedMemorySize, REC_SMEM);
        attr_set = 1;
    }

    conv_wfc<<<(int)(((size_t)V_ * H_ / 4) / 256), 256>>>(W_fc);
    conv_whh<<<(G4 * H_ / 4) / 256, 256>>>(W_hh);
    conv_wih<<<(G4 * D_ / 4) / 256, 256>>>(W_ih);
    conv_emb<<<TB, 128>>>(emb, gtruths);
    enc_pre_kernel<<<G4 / 32, 256>>>(encoder, W_ih, b_ih, b_hh);
    pre_mma<<<dim3(TB / 128, G4 / 128), 256>>>();
    rec_mma<<<128, 512, REC_SMEM>>>();
    logits_mma<<<dim3(TB / 128, V_ / 128), 256>>>(b_fc, out);
    if (out_size >= TB * V_ + TB)
        pred_finalize<<<(TB + 255) / 256, 256>>>(out + (size_t)TB * V_);
}

// round 17
// speedup vs baseline: 1.3011x; 1.0039x over previous
#include <cuda_runtime.h>
#include <cuda_bf16.h>
#include <math.h>
#include <stdint.h>

#define B_  32
#define T_  64
#define V_  32000
#define D_  512
#define E_  1024
#define H_  1024
#define G4  4096      // 4*H
#define TB  2048      // T*B
#define PA  1032      // padded row stride (bf16 elems) for rec smem tiles
#define PAD_ 40       // logits tile row pad (bf16)
#define NTILE_N 250   // V/128
#define NTILE_M 16    // TB/128
#define REC_BLOCKS 128
#define LOG_BLOCKS 2000   // 4000 tiles / 2 halves

// ---------------- device scratch (no allocations allowed) ----------------
__device__ float d_enc_pre[B_ * G4];                  // 0.5 MB
__device__ float d_pre[TB * G4];                      // 32 MB
__device__ unsigned g_bar;
__device__ __nv_bfloat16 d_Ah[TB * H_];               // 4 MB  hx hi
__device__ __nv_bfloat16 d_Al[TB * H_];               // 4 MB  hx lo
__device__ __nv_bfloat16 d_Bh[(size_t)V_ * H_];       // 64 MB W_fc hi
__device__ __nv_bfloat16 d_Bl[(size_t)V_ * H_];       // 64 MB W_fc lo
__device__ __nv_bfloat16 d_Wh[G4 * H_];               // 8 MB  W_hh hi
__device__ __nv_bfloat16 d_Wl[G4 * H_];               // 8 MB  W_hh lo
__device__ __nv_bfloat16 d_pAh[TB * D_];              // 2 MB  gathered emb hi
__device__ __nv_bfloat16 d_pAl[TB * D_];              // 2 MB  gathered emb lo
__device__ __nv_bfloat16 d_Wih_h[G4 * D_];            // 4 MB  W_ih[:,E:] hi
__device__ __nv_bfloat16 d_Wih_l[G4 * D_];            // 4 MB  W_ih[:,E:] lo
__device__ unsigned long long d_amax[TB];             // packed (val, ~col)

// ======================= PTX helpers (base-target, no 'a' features) ======
__device__ __forceinline__ uint32_t smem_u32(const void* p) {
    uint32_t a;
    asm("{ .reg .u64 t; cvta.to.shared.u64 t, %1; cvt.u32.u64 %0, t; }"
        : "=r"(a) : "l"(p));
    return a;
}
__device__ __forceinline__ void ldsm_x4(uint32_t& r0, uint32_t& r1,
                                        uint32_t& r2, uint32_t& r3, uint32_t a) {
    asm volatile("ldmatrix.sync.aligned.m8n8.x4.shared.b16 {%0,%1,%2,%3}, [%4];"
                 : "=r"(r0), "=r"(r1), "=r"(r2), "=r"(r3) : "r"(a));
}
__device__ __forceinline__ void mma16816(float* c,
    uint32_t a0, uint32_t a1, uint32_t a2, uint32_t a3, uint32_t b0, uint32_t b1) {
    asm volatile("mma.sync.aligned.m16n8k16.row.col.f32.bf16.bf16.f32 "
                 "{%0,%1,%2,%3}, {%4,%5,%6,%7}, {%8,%9}, {%0,%1,%2,%3};"
                 : "+f"(c[0]), "+f"(c[1]), "+f"(c[2]), "+f"(c[3])
                 : "r"(a0), "r"(a1), "r"(a2), "r"(a3), "r"(b0), "r"(b1));
}
__device__ __forceinline__ void cp_async16(uint32_t saddr, const void* gptr) {
    asm volatile("cp.async.cg.shared.global [%0], [%1], 16;"
                 :: "r"(saddr), "l"(gptr));
}
#define CP_COMMIT() asm volatile("cp.async.commit_group;" ::: "memory")
#define CP_WAIT0()  asm volatile("cp.async.wait_group 0;" ::: "memory")
#define CP_WAIT1()  asm volatile("cp.async.wait_group 1;" ::: "memory")
#define BAR_SYNC(id) asm volatile("bar.sync %0, %1;" :: "r"(id), "r"(256) : "memory")
// monotone float->uint (order-preserving)
__device__ __forceinline__ uint32_t fmono(float f) {
    uint32_t u = __float_as_uint(f);
    return (u & 0x80000000u) ? ~u : (u | 0x80000000u);
}
// fp32 -> (hi, lo) bf16 pair
__device__ __forceinline__ void bsplit(float v, __nv_bfloat16& h, __nv_bfloat16& l) {
    h = __float2bfloat16(v);
    l = __float2bfloat16(v - __bfloat162float(h));
}
struct bf4 { __nv_bfloat16 a, b, c, d; };

// ---------------- conversion kernels --------------------------------------
__global__ __launch_bounds__(256) void conv_wfc(const float* __restrict__ W)
{
    size_t i = (size_t)blockIdx.x * 256 + threadIdx.x;
    float4 v = ((const float4*)W)[i];
    bf4 h, l;
    bsplit(v.x, h.a, l.a); bsplit(v.y, h.b, l.b);
    bsplit(v.z, h.c, l.c); bsplit(v.w, h.d, l.d);
    *(bf4*)(d_Bh + 4 * i) = h;
    *(bf4*)(d_Bl + 4 * i) = l;
}
__global__ __launch_bounds__(256) void conv_whh(const float* __restrict__ W)
{
    size_t i = (size_t)blockIdx.x * 256 + threadIdx.x;
    float4 v = ((const float4*)W)[i];
    bf4 h, l;
    bsplit(v.x, h.a, l.a); bsplit(v.y, h.b, l.b);
    bsplit(v.z, h.c, l.c); bsplit(v.w, h.d, l.d);
    *(bf4*)(d_Wh + 4 * i) = h;
    *(bf4*)(d_Wl + 4 * i) = l;
}
__global__ __launch_bounds__(256) void conv_wih(const float* __restrict__ Wih)
{
    int idx = blockIdx.x * 256 + threadIdx.x;
    int j = idx >> 7, ci = idx & 127;
    float4 v = *(const float4*)(Wih + (size_t)j * (E_ + D_) + E_ + ci * 4);
    bf4 h, l;
    bsplit(v.x, h.a, l.a); bsplit(v.y, h.b, l.b);
    bsplit(v.z, h.c, l.c); bsplit(v.w, h.d, l.d);
    *(bf4*)(d_Wih_h + (size_t)j * D_ + ci * 4) = h;
    *(bf4*)(d_Wih_l + (size_t)j * D_ + ci * 4) = l;
}
__global__ __launch_bounds__(128) void conv_emb(
    const float* __restrict__ emb, const int* __restrict__ gt)
{
    int m = blockIdx.x;
    int tok = gt[(m & 31) * T_ + (m >> 5)];
    int i = threadIdx.x;
    float4 v = *(const float4*)(emb + (size_t)tok * D_ + i * 4);
    bf4 h, l;
    bsplit(v.x, h.a, l.a); bsplit(v.y, h.b, l.b);
    bsplit(v.z, h.c, l.c); bsplit(v.w, h.d, l.d);
    *(bf4*)(d_pAh + (size_t)m * D_ + i * 4) = h;
    *(bf4*)(d_pAl + (size_t)m * D_ + i * 4) = l;
}

// ---------------- enc_pre + replay-state init (fused) ---------------------
__global__ __launch_bounds__(256) void enc_pre_kernel(
    const float* __restrict__ enc, const float* __restrict__ Wih,
    const float* __restrict__ bih, const float* __restrict__ bhh)
{
    int tid = threadIdx.x;
    int gidx = blockIdx.x * 256 + tid;
    if (gidx < TB) d_amax[gidx] = 0ull;
    if (gidx == 0) g_bar = 0u;

    __shared__ float As[32][36];
    __shared__ float Bs[32][36];
    int j0  = blockIdx.x * 32;
    int lr  = tid >> 3, lk = (tid & 7) * 4;
    int col = tid & 31, rg = (tid >> 5) * 4;
    float acc[4] = {0.f, 0.f, 0.f, 0.f};

    for (int k0 = 0; k0 < E_; k0 += 32) {
        float4 av = *(const float4*)(enc + lr * E_ + k0 + lk);
        float4 bv = *(const float4*)(Wih + (size_t)(j0 + lr) * (E_ + D_) + k0 + lk);
        As[lk+0][lr] = av.x; As[lk+1][lr] = av.y; As[lk+2][lr] = av.z; As[lk+3][lr] = av.w;
        Bs[lk+0][lr] = bv.x; Bs[lk+1][lr] = bv.y; Bs[lk+2][lr] = bv.z; Bs[lk+3][lr] = bv.w;
        __syncthreads();
#pragma unroll
        for (int kk = 0; kk < 32; kk++) {
            float4 a = *(const float4*)&As[kk][rg];
            float  b = Bs[kk][col];
            acc[0] += a.x * b; acc[1] += a.y * b; acc[2] += a.z * b; acc[3] += a.w * b;
        }
        __syncthreads();
    }
    float bias = bih[j0 + col] + bhh[j0 + col];
#pragma unroll
    for (int i = 0; i < 4; i++)
        d_enc_pre[(rg + i) * G4 + j0 + col] = acc[i] + bias;
}

// ---------------- pre = emb_split @ Wih_split^T + enc_pre (mma.sync) ------
__global__ __launch_bounds__(256, 2) void pre_mma()
{
    __shared__ __align__(16) __nv_bfloat16 sA[2][128 * PAD_];
    __shared__ __align__(16) __nv_bfloat16 sB[2][128 * PAD_];

    int tid = threadIdx.x, lane = tid & 31, w = tid >> 5;
    int wm = w & 3, wn = w >> 2;
    int m0 = blockIdx.x * 128, n0 = blockIdx.y * 128;

    float c[2][8][4];
#pragma unroll
    for (int mi = 0; mi < 2; mi++)
#pragma unroll
        for (int ni = 0; ni < 8; ni++)
#pragma unroll
            for (int q = 0; q < 4; q++) c[mi][ni][q] = 0.f;

    int lrow = tid >> 2, lch = (tid & 3) * 8;

    uint4 pa[2], pb[2];
#pragma unroll
    for (int i = 0; i < 2; i++) {
        int row = lrow + i * 64;
        pa[i] = *(const uint4*)(d_pAh   + (size_t)(m0 + row) * D_ + lch);
        pb[i] = *(const uint4*)(d_Wih_h + (size_t)(n0 + row) * D_ + lch);
    }

    int a_col_l = (lane >> 4) * 8;
    int b_row_l = wn * 64 + ((lane >> 4) & 1) * 8 + (lane & 7);
    int b_col_l = ((lane >> 3) & 1) * 8;

    int buf = 0;
    for (int it = 0; it < 48; it++) {
#pragma unroll
        for (int i = 0; i < 2; i++) {
            int row = lrow + i * 64;
            *(uint4*)(&sA[buf][row * PAD_ + lch]) = pa[i];
            *(uint4*)(&sB[buf][row * PAD_ + lch]) = pb[i];
        }
        __syncthreads();

        if (it + 1 < 48) {
            int nit = it + 1;
            int seg = nit >> 4;
            int k0  = (nit & 15) * 32;
            const __nv_bfloat16* As = (seg == 1) ? d_pAl   : d_pAh;
            const __nv_bfloat16* Bs = (seg == 2) ? d_Wih_l : d_Wih_h;
#pragma unroll
            for (int i = 0; i < 2; i++) {
                int row = lrow + i * 64;
                pa[i] = *(const uint4*)(As + (size_t)(m0 + row) * D_ + k0 + lch);
                pb[i] = *(const uint4*)(Bs + (size_t)(n0 + row) * D_ + k0 + lch);
            }
        }

#pragma unroll
        for (int ks = 0; ks < 2; ks++) {
            uint32_t af[2][4];
#pragma unroll
            for (int mi = 0; mi < 2; mi++) {
                int row = wm * 32 + mi * 16 + (lane & 15);
                uint32_t a = smem_u32(&sA[buf][row * PAD_ + ks * 16 + a_col_l]);
                ldsm_x4(af[mi][0], af[mi][1], af[mi][2], af[mi][3], a);
            }
#pragma unroll
            for (int np = 0; np < 4; np++) {
                uint32_t b0, b1, b2, b3;
                uint32_t ba = smem_u32(
                    &sB[buf][(b_row_l + np * 16) * PAD_ + ks * 16 + b_col_l]);
                ldsm_x4(b0, b1, b2, b3, ba);
#pragma unroll
                for (int mi = 0; mi < 2; mi++) {
                    mma16816(c[mi][np * 2],     af[mi][0], af[mi][1], af[mi][2], af[mi][3], b0, b1);
                    mma16816(c[mi][np * 2 + 1], af[mi][0], af[mi][1], af[mi][2], af[mi][3], b2, b3);
                }
            }
        }
        buf ^= 1;
    }

#pragma unroll
    for (int mi = 0; mi < 2; mi++) {
#pragma unroll
        for (int ni = 0; ni < 8; ni++) {
            int row = m0 + wm * 32 + mi * 16 + (lane >> 2);
            int col = n0 + wn * 64 + ni * 8 + (lane & 3) * 2;
            float2 e0 = *(const float2*)&d_enc_pre[(row & 31) * G4 + col];
            float2 e1 = *(const float2*)&d_enc_pre[((row + 8) & 31) * G4 + col];
            float2 r0 = { c[mi][ni][0] + e0.x, c[mi][ni][1] + e0.y };
            float2 r1 = { c[mi][ni][2] + e1.x, c[mi][ni][3] + e1.y };
            *(float2*)&d_pre[(size_t)row * G4 + col]       = r0;
            *(float2*)&d_pre[(size_t)(row + 8) * G4 + col] = r1;
        }
    }
}

// ---------------- logits 128x128 tile (one 256-thread half) ---------------
// byte-identical math to the proven logits_mma; barriers are named (bar_id).
__device__ void logits_half(
    int tid, int bar_id, __nv_bfloat16* sbase,
    int m0, int n0, const float* __restrict__ bfc, float* __restrict__ out)
{
    __nv_bfloat16* sA = sbase;             // [2][128*PAD_]
    __nv_bfloat16* sB = sbase + 2 * 128 * PAD_;

    int lane = tid & 31, w = tid >> 5;
    int wm = w & 3, wn = w >> 2;

    float c[2][8][4];
#pragma unroll
    for (int mi = 0; mi < 2; mi++)
#pragma unroll
        for (int ni = 0; ni < 8; ni++)
#pragma unroll
            for (int q = 0; q < 4; q++) c[mi][ni][q] = 0.f;

    int lrow = tid >> 2, lch = (tid & 3) * 8;

    uint4 pa[2], pb[2];
#pragma unroll
    for (int i = 0; i < 2; i++) {
        int row = lrow + i * 64;
        pa[i] = *(const uint4*)(d_Ah + (size_t)(m0 + row) * H_ + lch);
        pb[i] = *(const uint4*)(d_Bh + (size_t)(n0 + row) * H_ + lch);
    }

    int a_col_l = (lane >> 4) * 8;
    int b_row_l = wn * 64 + ((lane >> 4) & 1) * 8 + (lane & 7);
    int b_col_l = ((lane >> 3) & 1) * 8;

    int buf = 0;
    for (int it = 0; it < 96; it++) {
        __nv_bfloat16* sAb = sA + buf * 128 * PAD_;
        __nv_bfloat16* sBb = sB + buf * 128 * PAD_;
#pragma unroll
        for (int i = 0; i < 2; i++) {
            int row = lrow + i * 64;
            *(uint4*)(&sAb[row * PAD_ + lch]) = pa[i];
            *(uint4*)(&sBb[row * PAD_ + lch]) = pb[i];
        }
        BAR_SYNC(bar_id);

        if (it + 1 < 96) {
            int nit = it + 1;
            int seg = nit >> 5;
            int k0  = (nit & 31) * 32;
            const __nv_bfloat16* As = (seg == 1) ? d_Al : d_Ah;
            const __nv_bfloat16* Bs = (seg == 2) ? d_Bl : d_Bh;
#pragma unroll
            for (int i = 0; i < 2; i++) {
                int row = lrow + i * 64;
                pa[i] = *(const uint4*)(As + (size_t)(m0 + row) * H_ + k0 + lch);
                pb[i] = *(const uint4*)(Bs + (size_t)(n0 + row) * H_ + k0 + lch);
            }
        }

#pragma unroll
        for (int ks = 0; ks < 2; ks++) {
            uint32_t af[2][4];
#pragma unroll
            for (int mi = 0; mi < 2; mi++) {
                int row = wm * 32 + mi * 16 + (lane & 15);
                uint32_t a = smem_u32(&sAb[row * PAD_ + ks * 16 + a_col_l]);
                ldsm_x4(af[mi][0], af[mi][1], af[mi][2], af[mi][3], a);
            }
#pragma unroll
            for (int np = 0; np < 4; np++) {
                uint32_t b0, b1, b2, b3;
                uint32_t ba = smem_u32(
                    &sBb[(b_row_l + np * 16) * PAD_ + ks * 16 + b_col_l]);
                ldsm_x4(b0, b1, b2, b3, ba);
#pragma unroll
                for (int mi = 0; mi < 2; mi++) {
                    mma16816(c[mi][np * 2],     af[mi][0], af[mi][1], af[mi][2], af[mi][3], b0, b1);
                    mma16816(c[mi][np * 2 + 1], af[mi][0], af[mi][1], af[mi][2], af[mi][3], b2, b3);
                }
            }
        }
        buf ^= 1;
    }

    // epilogue: store + fused per-row argmax via packed atomicMax
#pragma unroll
    for (int mi = 0; mi < 2; mi++) {
        unsigned long long key0 = 0ull, key1 = 0ull;
        int rbase = m0 + wm * 32 + mi * 16 + (lane >> 2);
#pragma unroll
        for (int ni = 0; ni < 8; ni++) {
            int col = n0 + wn * 64 + ni * 8 + (lane & 3) * 2;
            float2 bb = *(const float2*)&bfc[col];
            float2 r0 = { c[mi][ni][0] + bb.x, c[mi][ni][1] + bb.y };
            float2 r1 = { c[mi][ni][2] + bb.x, c[mi][ni][3] + bb.y };
            *(float2*)&out[(size_t)rbase * V_ + col]       = r0;
            *(float2*)&out[(size_t)(rbase + 8) * V_ + col] = r1;
            unsigned long long k;
            k = ((unsigned long long)fmono(r0.x) << 32) | (uint32_t)~col;
            if (k > key0) key0 = k;
            k = ((unsigned long long)fmono(r0.y) << 32) | (uint32_t)~(col + 1);
            if (k > key0) key0 = k;
            k = ((unsigned long long)fmono(r1.x) << 32) | (uint32_t)~col;
            if (k > key1) key1 = k;
            k = ((unsigned long long)fmono(r1.y) << 32) | (uint32_t)~(col + 1);
            if (k > key1) key1 = k;
        }
#pragma unroll
        for (int s = 1; s < 4; s <<= 1) {
            unsigned long long o0 = __shfl_xor_sync(0xFFFFFFFFu, key0, s);
            unsigned long long o1 = __shfl_xor_sync(0xFFFFFFFFu, key1, s);
            if (o0 > key0) key0 = o0;
            if (o1 > key1) key1 = o1;
        }
        if ((lane & 3) == 0) {
            atomicMax(&d_amax[rbase], key0);
            atomicMax(&d_amax[rbase + 8], key1);
        }
    }
}

// ---------------- uber kernel: rec (blocks<128) || gated logits -----------
__global__ __launch_bounds__(512, 1) void uber(
    const float* __restrict__ bfc, float* __restrict__ out)
{
    extern __shared__ __align__(16) __nv_bfloat16 sm[];

    if (blockIdx.x >= REC_BLOCKS) {
        // ---------------- progress-gated logits tile pair ----------------
        int half = threadIdx.x >> 8;           // 0 / 1
        int tid  = threadIdx.x & 255;
        int bar_id = 1 + half;
        int tau = (blockIdx.x - REC_BLOCKS) * 2 + half;
        int mt  = tau / NTILE_N;
        int m0  = mt * 128, n0 = (tau % NTILE_N) * 128;
        unsigned target = 512u * (unsigned)(mt + 1);  // = 128*(4*mt+4)

        if (tid == 0) {
            unsigned v;
            for (;;) {
                asm volatile("ld.acquire.gpu.global.u32 %0, [%1];"
                             : "=r"(v) : "l"(&g_bar) : "memory");
                if (v >= target) break;
                __nanosleep(256);
            }
        }
        BAR_SYNC(bar_id);

        logits_half(tid, bar_id, sm + half * (4 * 128 * PAD_), m0, n0, bfc, out);
        return;
    }

    // ---------------- persistent recurrence (rec v6) ----------------------
    __nv_bfloat16* sAh = sm;               // [32][PA] staged Ah (Wh at init)
    __nv_bfloat16* sAl = sm + 32 * PA;     // [32][PA] staged Al
    __nv_bfloat16* sBl = sm + 64 * PA;     // [32][PA] W_hh lo slice (resident)
    float* red = (float*)(sm + 32 * PA);   // overlays sAl after MMA reads

    int tid = threadIdx.x, lane = tid & 31, w = tid >> 5;
    int ks = w >> 1, ms = w & 1;
    int hbase = blockIdx.x * 8;
    uint32_t sAh_u = smem_u32(sAh);
    uint32_t sAl_u = smem_u32(sAl);
    uint32_t sBl_u = smem_u32(sBl);

    int a_off = (ms * 16 + (lane & 15)) * 2064 + ((lane >> 4) * 8) * 2;
    int b_row = ((lane >> 4) & 1) * 8 + (lane & 7);
    int b_off0 = b_row * 2064 + (((lane >> 3) & 1) * 8) * 2;
    int b_off1 = (b_row + 16) * 2064 + (((lane >> 3) & 1) * 8) * 2;
    int kbase = ks * 128;

    // ---- init: stage Wh into sAh, Wl into sBl ----
#pragma unroll
    for (int i = 0; i < 8; i++) {
        int ch = tid + i * 512;
        int row = ch >> 7, co = ch & 127;
        int jc = (row >> 3) * H_ + hbase + (row & 7);
        cp_async16(sAh_u + row * 2064 + co * 16, d_Wh + (size_t)jc * H_ + co * 8);
        cp_async16(sBl_u + row * 2064 + co * 16, d_Wl + (size_t)jc * H_ + co * 8);
    }
    CP_COMMIT(); CP_WAIT0();
    __syncthreads();

    uint32_t bh[8][8];
#pragma unroll
    for (int kk = 0; kk < 8; kk++) {
        int cb = (kbase + kk * 16) * 2;
        ldsm_x4(bh[kk][0], bh[kk][1], bh[kk][2], bh[kk][3], sAh_u + b_off0 + cb);
        ldsm_x4(bh[kk][4], bh[kk][5], bh[kk][6], bh[kk][7], sAh_u + b_off1 + cb);
    }
    __syncthreads();

    int b_own = tid >> 3, hh_own = tid & 7;
    int hcol_own = hbase + hh_own;
    float creg = 0.f;

    for (int t = 0; t < T_; t++) {
        float p0 = 0.f, p1 = 0.f, p2 = 0.f, p3 = 0.f;
        if (tid < 256) {
            const float* pp = d_pre + ((size_t)(t * B_ + b_own)) * G4 + hcol_own;
            p0 = __ldg(pp);            p1 = __ldg(pp + H_);
            p2 = __ldg(pp + 2 * H_);   p3 = __ldg(pp + 3 * H_);
        }

        if (t > 0) {
            // ---- stage Ah (group 0) and Al (group 1); overlap Al arrival ---
            const __nv_bfloat16* Ah_src = d_Ah + (size_t)(t - 1) * (B_ * H_);
            const __nv_bfloat16* Al_src = d_Al + (size_t)(t - 1) * (B_ * H_);
#pragma unroll
            for (int i = 0; i < 8; i++) {
                int ch = tid + i * 512;
                int row = ch >> 7, co = ch & 127;
                cp_async16(sAh_u + row * 2064 + co * 16, Ah_src + row * H_ + co * 8);
            }
            CP_COMMIT();
#pragma unroll
            for (int i = 0; i < 8; i++) {
                int ch = tid + i * 512;
                int row = ch >> 7, co = ch & 127;
                cp_async16(sAl_u + row * 2064 + co * 16, Al_src + row * H_ + co * 8);
            }
            CP_COMMIT();
            CP_WAIT1();           // Ah ready
            __syncthreads();

            float acc[4][4];
#pragma unroll
            for (int ni = 0; ni < 4; ni++)
#pragma unroll
                for (int q = 0; q < 4; q++) acc[ni][q] = 0.f;

            // Ah passes: Ah*Bh + Ah*Bl (8 MMA/kk) — Al still in flight
#pragma unroll
            for (int kk = 0; kk < 8; kk++) {
                int cb = (kbase + kk * 16) * 2;
                uint32_t a0, a1, a2, a3;
                ldsm_x4(a0, a1, a2, a3, sAh_u + a_off + cb);
                mma16816(acc[0], a0, a1, a2, a3, bh[kk][0], bh[kk][1]);
                mma16816(acc[1], a0, a1, a2, a3, bh[kk][2], bh[kk][3]);
                mma16816(acc[2], a0, a1, a2, a3, bh[kk][4], bh[kk][5]);
                mma16816(acc[3], a0, a1, a2, a3, bh[kk][6], bh[kk][7]);
                uint32_t c0, c1, c2, c3, c4, c5, c6, c7;
                ldsm_x4(c0, c1, c2, c3, sBl_u + b_off0 + cb);
                ldsm_x4(c4, c5, c6, c7, sBl_u + b_off1 + cb);
                mma16816(acc[0], a0, a1, a2, a3, c0, c1);
                mma16816(acc[1], a0, a1, a2, a3, c2, c3);
                mma16816(acc[2], a0, a1, a2, a3, c4, c5);
                mma16816(acc[3], a0, a1, a2, a3, c6, c7);
            }
            CP_WAIT0();           // Al ready
            __syncthreads();

            // Al pass: Al*Bh (4 MMA/kk)
#pragma unroll
            for (int kk = 0; kk < 8; kk++) {
                int cb = (kbase + kk * 16) * 2;
                uint32_t l0, l1, l2, l3;
                ldsm_x4(l0, l1, l2, l3, sAl_u + a_off + cb);
                mma16816(acc[0], l0, l1, l2, l3, bh[kk][0], bh[kk][1]);
                mma16816(acc[1], l0, l1, l2, l3, bh[kk][2], bh[kk][3]);
                mma16816(acc[2], l0, l1, l2, l3, bh[kk][4], bh[kk][5]);
                mma16816(acc[3], l0, l1, l2, l3, bh[kk][6], bh[kk][7]);
            }
            __syncthreads();   // all sAl reads done before red overlay write

            // ---- store partials: red[ms][ks][m16row][32col] (on sAl) ----
            float* rw = red + ((ms * 8 + ks) * 16) * 32;
#pragma unroll
            for (int ni = 0; ni < 4; ni++) {
                int col = ni * 8 + (lane & 3) * 2;
                int r0i = (lane >> 2);
                *(float2*)&rw[r0i * 32 + col]       = make_float2(acc[ni][0], acc[ni][1]);
                *(float2*)&rw[(r0i + 8) * 32 + col] = make_float2(acc[ni][2], acc[ni][3]);
            }
            __syncthreads();
        }

        // ---- cell update ----
        if (tid < 256) {
            float gi = 0.f, gf = 0.f, gg = 0.f, go = 0.f;
            if (t > 0) {
                int msb = b_own >> 4, mr = b_own & 15;
#pragma unroll
                for (int kq = 0; kq < 8; kq++) {
                    const float* r = red + (((msb * 8 + kq) * 16) + mr) * 32;
                    gi += r[hh_own];      gf += r[8  + hh_own];
                    gg += r[16 + hh_own]; go += r[24 + hh_own];
                }
            }
            gi += p0; gf += p1; gg += p2; go += p3;
            float si = 1.f / (1.f + expf(-gi));
            float sf = 1.f / (1.f + expf(-gf));
            float so = 1.f / (1.f + expf(-go));
            creg = sf * creg + si * tanhf(gg);
            float hn = so * tanhf(creg);
            __nv_bfloat16 ah = __float2bfloat16(hn);
            __nv_bfloat16 al = __float2bfloat16(hn - __bfloat162float(ah));
            size_t arow = (size_t)(t * B_ + b_own) * H_ + hcol_own;
            d_Ah[arow] = ah; d_Al[arow] = al;
        }

        // grid barrier: release/acquire, tid0 only (also publishes progress
        // to the gated logits blocks via the same counter)
        __syncthreads();
        if (tid == 0) {
            asm volatile("red.release.gpu.global.add.u32 [%0], %1;"
                         :: "l"(&g_bar), "r"(1u) : "memory");
            unsigned target = 128u * (unsigned)(t + 1);
            unsigned v;
            do {
                asm volatile("ld.acquire.gpu.global.u32 %0, [%1];"
                             : "=r"(v) : "l"(&g_bar) : "memory");
            } while (v < target);
        }
        __syncthreads();
    }
}

// ---------------- finalize predic from packed argmax ----------------------
__global__ __launch_bounds__(256) void pred_finalize(float* __restrict__ pred)
{
    int m = blockIdx.x * 256 + threadIdx.x;
    if (m >= TB) return;
    unsigned col = ~(unsigned)(d_amax[m] & 0xFFFFFFFFull);
    int t = m >> 5, b = m & 31;
    pred[b * T_ + t] = (float)col;
}

// ------------------------------------------------------------------------
extern "C" void kernel_launch(void* const* d_in, const int* in_sizes, int n_in,
                              void* d_out, int out_size)
{
    const float* encoder = (const float*)d_in[0];
    const int*   gtruths = (const int*)  d_in[1];
    const float* emb     = (const float*)d_in[2];
    const float* W_ih    = (const float*)d_in[3];
    const float* W_hh    = (const float*)d_in[4];
    const float* b_ih    = (const float*)d_in[5];
    const float* b_hh    = (const float*)d_in[6];
    const float* W_fc    = (const float*)d_in[7];
    const float* b_fc    = (const float*)d_in[8];
    float* out = (float*)d_out;

    const int REC_SMEM = 96 * PA * 2;   // 198144 B (covers 2x logits halves too)

    static int attr_set = 0;
    if (!attr_set) {
        cudaFuncSetAttribute(uber,
                             cudaFuncAttributeMaxDynamicSharedMemorySize, REC_SMEM);
        attr_set = 1;
    }

    conv_wfc<<<(int)(((size_t)V_ * H_ / 4) / 256), 256>>>(W_fc);
    conv_whh<<<(G4 * H_ / 4) / 256, 256>>>(W_hh);
    conv_wih<<<(G4 * D_ / 4) / 256, 256>>>(W_ih);
    conv_emb<<<TB, 128>>>(emb, gtruths);
    enc_pre_kernel<<<G4 / 32, 256>>>(encoder, W_ih, b_ih, b_hh);
    pre_mma<<<dim3(TB / 128, G4 / 128), 256>>>();
    uber<<<REC_BLOCKS + LOG_BLOCKS, 512, REC_SMEM>>>(b_fc, out);
    if (out_size >= TB * V_ + TB)
        pred_finalize<<<(TB + 255) / 256, 256>>>(out + (size_t)TB * V_);
}